// round 3
// baseline (speedup 1.0000x reference)
#include <cuda_runtime.h>
#include <cuda_bf16.h>

// Problem constants
#define BATCH 512
#define SEQ   256
#define CEMB  384
#define HEAD  64
#define MROWS (BATCH * SEQ)          // 131072
#define NQKV  (3 * HEAD)             // 192 (Q|K|V concatenated)
#define SCALE 0.05103103630798288f   // 384^-0.5

// Scratch: [row][192] = [Q(64) | K(64) | V(64)] per (b,t) row.  ~100.7 MB.
__device__ float g_QKV[(size_t)MROWS * NQKV];

// ---------------------------------------------------------------------------
// Kernel 1: fused QKV projection.
// C = x @ [Wq|Wk|Wv] : [131072 x 384] @ [384 x 192]
// BM=64, BN=192, BK=32, 256 threads, each thread computes 4x12 outputs.
// ---------------------------------------------------------------------------
__global__ __launch_bounds__(256) void qkv_kernel(
    const float* __restrict__ x,
    const float* __restrict__ Wq,
    const float* __restrict__ Wk,
    const float* __restrict__ Wv)
{
    __shared__ float xs[32 * 65];    // [kk][row], padded (write stride-64 -> conflict w/o pad)
    __shared__ float ws[32 * 192];   // [kk][n]

    const int tid = threadIdx.x;
    const int tx  = tid & 15;        // output col group: cols tx + 16*c, c=0..11
    const int ty  = tid >> 4;        // output row group: rows ty + 16*r, r=0..3
    const int row0 = blockIdx.x * 64;

    float acc[4][12];
#pragma unroll
    for (int r = 0; r < 4; r++)
#pragma unroll
        for (int c = 0; c < 12; c++) acc[r][c] = 0.0f;

    for (int k0 = 0; k0 < CEMB; k0 += 32) {
        // Load x tile: 64 rows x 32 k -> xs[kk][row]. 2048 elems, 8/thread.
        // Warp reads one row's 32 contiguous floats (coalesced).
#pragma unroll
        for (int i = 0; i < 8; i++) {
            int li = tid + i * 256;
            int r  = li >> 5;
            int c  = li & 31;
            xs[c * 65 + r] = x[(size_t)(row0 + r) * CEMB + k0 + c];
        }
        // Load W tile: 32 k x 192 n. 6144 elems, 24/thread, coalesced in n.
#pragma unroll
        for (int i = 0; i < 24; i++) {
            int li = tid + i * 256;
            int kk = li / 192;
            int n  = li % 192;
            float v;
            if (n < 64)        v = Wq[(k0 + kk) * HEAD + n];
            else if (n < 128)  v = Wk[(k0 + kk) * HEAD + (n - 64)];
            else               v = Wv[(k0 + kk) * HEAD + (n - 128)];
            ws[kk * 192 + n] = v;
        }
        __syncthreads();

#pragma unroll
        for (int kk = 0; kk < 32; kk++) {
            float a[4], b[12];
#pragma unroll
            for (int r = 0; r < 4; r++) a[r] = xs[kk * 65 + ty + 16 * r];
#pragma unroll
            for (int c = 0; c < 12; c++) b[c] = ws[kk * 192 + tx + 16 * c];
#pragma unroll
            for (int r = 0; r < 4; r++)
#pragma unroll
                for (int c = 0; c < 12; c++)
                    acc[r][c] = fmaf(a[r], b[c], acc[r][c]);
        }
        __syncthreads();
    }

    // Store to scratch
#pragma unroll
    for (int r = 0; r < 4; r++) {
        size_t base = (size_t)(row0 + ty + 16 * r) * NQKV;
#pragma unroll
        for (int c = 0; c < 12; c++)
            g_QKV[base + tx + 16 * c] = acc[r][c];
    }
}

// ---------------------------------------------------------------------------
// Kernel 2: causal attention for one (batch, 64-row tile).
// grid = (4 row-tiles, 512 batches), 256 threads.
// smem: Q[64][65], K[64][65], V[256][64], P[64][257]  (~164.6 KB dynamic)
// Two-pass: build the full masked score strip S[64 x ncols] in smem,
// softmax it in place, then O = P @ V.
// ---------------------------------------------------------------------------
#define SQ_F  (64 * 65)
#define SK_F  (64 * 65)
#define SV_F  (256 * 64)
#define SP_F  (64 * 257)
#define ATTN_SMEM_BYTES ((SQ_F + SK_F + SV_F + SP_F) * sizeof(float))

__global__ __launch_bounds__(256) void attn_kernel(float* __restrict__ out)
{
    extern __shared__ float sm[];
    float* sQ = sm;                 // [row][kk] stride 65
    float* sK = sQ + SQ_F;          // [col][kk] stride 65
    float* sV = sK + SK_F;          // [j][d]    stride 64
    float* sP = sV + SV_F;          // [row][j]  stride 257

    const int tid   = threadIdx.x;
    const int tx    = tid & 15;     // col/dim group
    const int ty    = tid >> 4;     // row group
    const int rt    = blockIdx.x;   // row tile 0..3
    const int batch = blockIdx.y;
    const int r0    = rt * 64;
    const int ncols = (rt + 1) * 64;
    const size_t brow = (size_t)batch * SEQ;   // first global row of batch

    // Load Q tile (offset 0) and full V (offset 128).
#pragma unroll
    for (int i = 0; i < 16; i++) {
        int li = tid + i * 256;
        int r = li >> 6, c = li & 63;
        sQ[r * 65 + c] = g_QKV[(brow + r0 + r) * NQKV + c];
    }
#pragma unroll
    for (int i = 0; i < 64; i++) {
        int li = tid + i * 256;
        int r = li >> 6, c = li & 63;
        sV[r * 64 + c] = g_QKV[(brow + r) * NQKV + 128 + c];
    }

    // ---- Pass 1: scores S = scale * Q K^T with causal mask, into sP ----
    for (int kc = 0; kc <= rt; kc++) {
        // Load K tile (offset 64)
#pragma unroll
        for (int i = 0; i < 16; i++) {
            int li = tid + i * 256;
            int r = li >> 6, c = li & 63;
            sK[r * 65 + c] = g_QKV[(brow + kc * 64 + r) * NQKV + 64 + c];
        }
        __syncthreads();

        float accS[4][4];
#pragma unroll
        for (int r = 0; r < 4; r++)
#pragma unroll
            for (int c = 0; c < 4; c++) accS[r][c] = 0.0f;

#pragma unroll 4
        for (int kk = 0; kk < 64; kk++) {
            float a[4], b[4];
#pragma unroll
            for (int r = 0; r < 4; r++) a[r] = sQ[(ty + 16 * r) * 65 + kk];
#pragma unroll
            for (int c = 0; c < 4; c++) b[c] = sK[(tx + 16 * c) * 65 + kk];
#pragma unroll
            for (int r = 0; r < 4; r++)
#pragma unroll
                for (int c = 0; c < 4; c++)
                    accS[r][c] = fmaf(a[r], b[c], accS[r][c]);
        }

#pragma unroll
        for (int r = 0; r < 4; r++) {
            int gi = r0 + ty + 16 * r;
#pragma unroll
            for (int c = 0; c < 4; c++) {
                int gj = kc * 64 + tx + 16 * c;
                float v = (gj <= gi) ? accS[r][c] * SCALE : -1e30f;
                sP[(ty + 16 * r) * 257 + gj] = v;
            }
        }
        __syncthreads();
    }

    // ---- Softmax: warp w handles rows w*8 .. w*8+7 ----
    {
        const int warp = tid >> 5, lane = tid & 31;
        for (int rr = 0; rr < 8; rr++) {
            int row = warp * 8 + rr;
            float* prow = sP + row * 257;
            float m = -1e30f;
            for (int j = lane; j < ncols; j += 32) m = fmaxf(m, prow[j]);
#pragma unroll
            for (int off = 16; off > 0; off >>= 1)
                m = fmaxf(m, __shfl_xor_sync(0xffffffffu, m, off));
            float s = 0.0f;
            for (int j = lane; j < ncols; j += 32) {
                float e = __expf(prow[j] - m);
                prow[j] = e;
                s += e;
            }
#pragma unroll
            for (int off = 16; off > 0; off >>= 1)
                s += __shfl_xor_sync(0xffffffffu, s, off);
            float inv = 1.0f / s;
            for (int j = lane; j < ncols; j += 32) prow[j] *= inv;
        }
    }
    __syncthreads();

    // ---- Pass 2: O = P @ V ----
    float accO[4][4];
#pragma unroll
    for (int r = 0; r < 4; r++)
#pragma unroll
        for (int d = 0; d < 4; d++) accO[r][d] = 0.0f;

#pragma unroll 2
    for (int j = 0; j < ncols; j++) {
        float p[4], v[4];
#pragma unroll
        for (int r = 0; r < 4; r++) p[r] = sP[(ty + 16 * r) * 257 + j];
#pragma unroll
        for (int d = 0; d < 4; d++) v[d] = sV[j * 64 + tx + 16 * d];
#pragma unroll
        for (int r = 0; r < 4; r++)
#pragma unroll
            for (int d = 0; d < 4; d++)
                accO[r][d] = fmaf(p[r], v[d], accO[r][d]);
    }

#pragma unroll
    for (int r = 0; r < 4; r++) {
        size_t base = (brow + r0 + ty + 16 * r) * (size_t)HEAD;
#pragma unroll
        for (int d = 0; d < 4; d++)
            out[base + tx + 16 * d] = accO[r][d];
    }
}

// ---------------------------------------------------------------------------
extern "C" void kernel_launch(void* const* d_in, const int* in_sizes, int n_in,
                              void* d_out, int out_size)
{
    const float* x  = (const float*)d_in[0];
    const float* Wq = (const float*)d_in[1];
    const float* Wk = (const float*)d_in[2];
    const float* Wv = (const float*)d_in[3];
    float* out = (float*)d_out;

    (void)in_sizes; (void)n_in; (void)out_size;

    cudaFuncSetAttribute(attn_kernel,
                         cudaFuncAttributeMaxDynamicSharedMemorySize,
                         (int)ATTN_SMEM_BYTES);

    qkv_kernel<<<MROWS / 64, 256>>>(x, Wq, Wk, Wv);
    attn_kernel<<<dim3(4, BATCH), 256, ATTN_SMEM_BYTES>>>(out);
}

// round 5
// speedup vs baseline: 2.7860x; 2.7860x over previous
#include <cuda_runtime.h>
#include <cuda_bf16.h>
#include <cstdint>

// Problem constants
#define BATCH 512
#define SEQ   256
#define CEMB  384
#define HEAD  64
#define MROWS (BATCH * SEQ)          // 131072
#define NQKV  (3 * HEAD)             // 192 (Q|K|V concatenated)
#define SCALE 0.05103103630798288f   // 384^-0.5

// Scratch buffers (__device__ globals: no allocs allowed)
__device__ float g_QKV[(size_t)MROWS * NQKV];                 // [row][Q|K|V]
__device__ __nv_bfloat16 g_Xhi[(size_t)MROWS * CEMB];         // x split hi
__device__ __nv_bfloat16 g_Xlo[(size_t)MROWS * CEMB];         // x split lo
__device__ __nv_bfloat16 g_WThi[NQKV * CEMB];                 // W^T split hi [n][k]
__device__ __nv_bfloat16 g_WTlo[NQKV * CEMB];                 // W^T split lo [n][k]

// ---------------------------------------------------------------------------
// Warp-MMA helpers (baseline PTX, legal on .target sm_103 — NOT tcgen05)
// ---------------------------------------------------------------------------
__device__ __forceinline__ uint32_t smem_to_u32(const void* p) {
    uint32_t a;
    asm("{ .reg .u64 t; cvta.to.shared.u64 t, %1; cvt.u32.u64 %0, t; }"
        : "=r"(a) : "l"(p));
    return a;
}

#define LDSM_X4(r0, r1, r2, r3, addr) \
    asm volatile("ldmatrix.sync.aligned.m8n8.x4.shared.b16 {%0,%1,%2,%3}, [%4];" \
        : "=r"(r0), "=r"(r1), "=r"(r2), "=r"(r3) : "r"(addr))

#define MMA16816(d, a, b0, b1) \
    asm volatile("mma.sync.aligned.m16n8k16.row.col.f32.bf16.bf16.f32 " \
        "{%0,%1,%2,%3}, {%4,%5,%6,%7}, {%8,%9}, {%0,%1,%2,%3};" \
        : "+f"((d)[0]), "+f"((d)[1]), "+f"((d)[2]), "+f"((d)[3]) \
        : "r"((a)[0]), "r"((a)[1]), "r"((a)[2]), "r"((a)[3]), \
          "r"(b0), "r"(b1))

// ---------------------------------------------------------------------------
// Prep: x -> bf16 hi/lo split (vectorized, memory-bound)
// ---------------------------------------------------------------------------
__global__ __launch_bounds__(256) void xprep_kernel(const float* __restrict__ x)
{
    size_t i = (size_t)blockIdx.x * 256 + threadIdx.x;   // < 12582912 exact
    float4 v = ((const float4*)x)[i];
    __nv_bfloat16 h0 = __float2bfloat16(v.x);
    __nv_bfloat16 h1 = __float2bfloat16(v.y);
    __nv_bfloat16 h2 = __float2bfloat16(v.z);
    __nv_bfloat16 h3 = __float2bfloat16(v.w);
    __nv_bfloat16 l0 = __float2bfloat16(v.x - __bfloat162float(h0));
    __nv_bfloat16 l1 = __float2bfloat16(v.y - __bfloat162float(h1));
    __nv_bfloat16 l2 = __float2bfloat16(v.z - __bfloat162float(h2));
    __nv_bfloat16 l3 = __float2bfloat16(v.w - __bfloat162float(h3));
    __nv_bfloat162 hp0 = __halves2bfloat162(h0, h1);
    __nv_bfloat162 hp1 = __halves2bfloat162(h2, h3);
    __nv_bfloat162 lp0 = __halves2bfloat162(l0, l1);
    __nv_bfloat162 lp1 = __halves2bfloat162(l2, l3);
    uint2 hw, lw;
    hw.x = *(uint32_t*)&hp0;  hw.y = *(uint32_t*)&hp1;
    lw.x = *(uint32_t*)&lp0;  lw.y = *(uint32_t*)&lp1;
    ((uint2*)g_Xhi)[i] = hw;
    ((uint2*)g_Xlo)[i] = lw;
}

// Prep: W^T + bf16 hi/lo split.  g_WT[n][k] = W[k][n], n = mat*64 + h
__global__ void wprep_kernel(const float* __restrict__ Wq,
                             const float* __restrict__ Wk,
                             const float* __restrict__ Wv)
{
    int idx = blockIdx.x * 256 + threadIdx.x;
    if (idx >= NQKV * CEMB) return;
    int n = idx / CEMB, k = idx % CEMB;
    int mat = n >> 6, h = n & 63;
    const float* W = (mat == 0) ? Wq : (mat == 1) ? Wk : Wv;
    float v = W[k * HEAD + h];
    __nv_bfloat16 hi = __float2bfloat16(v);
    g_WThi[idx] = hi;
    g_WTlo[idx] = __float2bfloat16(v - __bfloat162float(hi));
}

// ---------------------------------------------------------------------------
// QKV projection via warp mma (HMMA), bf16 split-accumulate:
//   C = Ahi*Bhi + Ahi*Blo + Alo*Bhi   (fp32 accumulators)
// BM=128, BN=192, BK=32, 256 threads; warps 4(M) x 2(N), warp tile 32x96.
// smem rows padded to 40 bf16 (80 B) -> conflict-free ldmatrix.
// ---------------------------------------------------------------------------
#define QPAD 40
#define SOFF_AHI 0
#define SOFF_ALO (128 * QPAD)
#define SOFF_BHI (2 * 128 * QPAD)
#define SOFF_BLO (2 * 128 * QPAD + 192 * QPAD)
#define QKV_SMEM_ELEMS (2 * 128 * QPAD + 2 * 192 * QPAD)    // 25600 bf16
#define QKV_SMEM_BYTES (QKV_SMEM_ELEMS * 2)                 // 51200 B

__global__ __launch_bounds__(256) void qkv_mma_kernel()
{
    extern __shared__ __nv_bfloat16 smq[];
    const uint32_t sbase = smem_to_u32(smq);
    const int tid   = threadIdx.x;
    const int lane  = tid & 31;
    const int wid   = tid >> 5;
    const int warpM = wid & 3;        // 0..3  -> rows warpM*32
    const int warpN = wid >> 2;       // 0..1  -> cols warpN*96
    const int row0  = blockIdx.x * 128;

    // ldmatrix lane addressing: 16 lanes pick rows, upper 16 shift k by 8
    const int laneRow = lane & 15;
    const int laneK   = (lane >> 4) << 3;

    float acc[2][12][4];
#pragma unroll
    for (int mt = 0; mt < 2; mt++)
#pragma unroll
        for (int nt = 0; nt < 12; nt++)
#pragma unroll
            for (int e = 0; e < 4; e++) acc[mt][nt][e] = 0.0f;

    for (int chunk = 0; chunk < 12; chunk++) {
        const int k0 = chunk * 32;

        // --- A tiles: 128 rows x 32 k, hi+lo. 1024 u64 each, 4/thread ---
#pragma unroll
        for (int i = 0; i < 4; i++) {
            int li = tid + i * 256;
            int r = li >> 3, g = li & 7;           // 8 u64-groups per row
            size_t srcByte = ((size_t)(row0 + r) * CEMB + k0 + g * 4);
            uint2 hv = *(const uint2*)&g_Xhi[srcByte];
            uint2 lv = *(const uint2*)&g_Xlo[srcByte];
            *(uint2*)&smq[SOFF_AHI + r * QPAD + g * 4] = hv;
            *(uint2*)&smq[SOFF_ALO + r * QPAD + g * 4] = lv;
        }
        // --- B tiles: 192 rows x 32 k, hi+lo. 1536 u64 each, 6/thread ---
#pragma unroll
        for (int i = 0; i < 6; i++) {
            int li = tid + i * 256;
            int r = li >> 3, g = li & 7;
            size_t srcByte = ((size_t)r * CEMB + k0 + g * 4);
            uint2 hv = *(const uint2*)&g_WThi[srcByte];
            uint2 lv = *(const uint2*)&g_WTlo[srcByte];
            *(uint2*)&smq[SOFF_BHI + r * QPAD + g * 4] = hv;
            *(uint2*)&smq[SOFF_BLO + r * QPAD + g * 4] = lv;
        }
        __syncthreads();

#pragma unroll
        for (int ks = 0; ks < 2; ks++) {
            const int kk = ks * 16 + laneK;
            // A fragments (hi and lo), hoisted across the 3 passes
            uint32_t ahi[2][4], alo[2][4];
#pragma unroll
            for (int mt = 0; mt < 2; mt++) {
                uint32_t off = (uint32_t)((warpM * 32 + mt * 16 + laneRow) * QPAD + kk) * 2;
                LDSM_X4(ahi[mt][0], ahi[mt][1], ahi[mt][2], ahi[mt][3],
                        sbase + SOFF_AHI * 2 + off);
                LDSM_X4(alo[mt][0], alo[mt][1], alo[mt][2], alo[mt][3],
                        sbase + SOFF_ALO * 2 + off);
            }
            // Passes: (Ahi,Bhi), (Ahi,Blo), (Alo,Bhi)
#pragma unroll
            for (int p = 0; p < 3; p++) {
                const uint32_t bOffBase = (p == 1) ? (uint32_t)(SOFF_BLO * 2)
                                                   : (uint32_t)(SOFF_BHI * 2);
                uint32_t (*A)[4] = (p < 2) ? ahi : alo;
                uint32_t bf[6][4];
#pragma unroll
                for (int j = 0; j < 6; j++) {
                    uint32_t off = (uint32_t)((warpN * 96 + j * 16 + laneRow) * QPAD + kk) * 2;
                    LDSM_X4(bf[j][0], bf[j][1], bf[j][2], bf[j][3],
                            sbase + bOffBase + off);
                }
#pragma unroll
                for (int mt = 0; mt < 2; mt++)
#pragma unroll
                    for (int j = 0; j < 6; j++) {
                        MMA16816(acc[mt][2 * j],     A[mt], bf[j][0], bf[j][2]);
                        MMA16816(acc[mt][2 * j + 1], A[mt], bf[j][1], bf[j][3]);
                    }
            }
        }
        __syncthreads();
    }

    // --- Epilogue: fragment -> g_QKV (float2 per write) ---
    const int qrow = lane >> 2;
    const int qcol = (lane & 3) * 2;
#pragma unroll
    for (int mt = 0; mt < 2; mt++) {
#pragma unroll
        for (int h = 0; h < 2; h++) {
            int row = row0 + warpM * 32 + mt * 16 + qrow + 8 * h;
            size_t base = (size_t)row * NQKV + warpN * 96 + qcol;
#pragma unroll
            for (int j = 0; j < 12; j++) {
                float2 v = make_float2(acc[mt][j][2 * h], acc[mt][j][2 * h + 1]);
                *(float2*)&g_QKV[base + j * 8] = v;
            }
        }
    }
}

// ---------------------------------------------------------------------------
// Kernel 2: causal attention (unchanged, known good)
// ---------------------------------------------------------------------------
#define SQ_F  (64 * 65)
#define SK_F  (64 * 65)
#define SV_F  (256 * 64)
#define SP_F  (64 * 257)
#define ATTN_SMEM_BYTES ((SQ_F + SK_F + SV_F + SP_F) * sizeof(float))

__global__ __launch_bounds__(256) void attn_kernel(float* __restrict__ out)
{
    extern __shared__ float smf[];
    float* sQ = smf;
    float* sK = sQ + SQ_F;
    float* sV = sK + SK_F;
    float* sP = sV + SV_F;

    const int tid   = threadIdx.x;
    const int tx    = tid & 15;
    const int ty    = tid >> 4;
    const int rt    = blockIdx.x;
    const int batch = blockIdx.y;
    const int r0    = rt * 64;
    const int ncols = (rt + 1) * 64;
    const size_t brow = (size_t)batch * SEQ;

#pragma unroll
    for (int i = 0; i < 16; i++) {
        int li = tid + i * 256;
        int r = li >> 6, c = li & 63;
        sQ[r * 65 + c] = g_QKV[(brow + r0 + r) * NQKV + c];
    }
#pragma unroll
    for (int i = 0; i < 64; i++) {
        int li = tid + i * 256;
        int r = li >> 6, c = li & 63;
        sV[r * 64 + c] = g_QKV[(brow + r) * NQKV + 128 + c];
    }

    for (int kc = 0; kc <= rt; kc++) {
#pragma unroll
        for (int i = 0; i < 16; i++) {
            int li = tid + i * 256;
            int r = li >> 6, c = li & 63;
            sK[r * 65 + c] = g_QKV[(brow + kc * 64 + r) * NQKV + 64 + c];
        }
        __syncthreads();

        float accS[4][4];
#pragma unroll
        for (int r = 0; r < 4; r++)
#pragma unroll
            for (int c = 0; c < 4; c++) accS[r][c] = 0.0f;

#pragma unroll 4
        for (int kk = 0; kk < 64; kk++) {
            float a[4], b[4];
#pragma unroll
            for (int r = 0; r < 4; r++) a[r] = sQ[(ty + 16 * r) * 65 + kk];
#pragma unroll
            for (int c = 0; c < 4; c++) b[c] = sK[(tx + 16 * c) * 65 + kk];
#pragma unroll
            for (int r = 0; r < 4; r++)
#pragma unroll
                for (int c = 0; c < 4; c++)
                    accS[r][c] = fmaf(a[r], b[c], accS[r][c]);
        }

#pragma unroll
        for (int r = 0; r < 4; r++) {
            int gi = r0 + ty + 16 * r;
#pragma unroll
            for (int c = 0; c < 4; c++) {
                int gj = kc * 64 + tx + 16 * c;
                float v = (gj <= gi) ? accS[r][c] * SCALE : -1e30f;
                sP[(ty + 16 * r) * 257 + gj] = v;
            }
        }
        __syncthreads();
    }

    {
        const int warp = tid >> 5, lane = tid & 31;
        for (int rr = 0; rr < 8; rr++) {
            int row = warp * 8 + rr;
            float* prow = sP + row * 257;
            float m = -1e30f;
            for (int j = lane; j < ncols; j += 32) m = fmaxf(m, prow[j]);
#pragma unroll
            for (int off = 16; off > 0; off >>= 1)
                m = fmaxf(m, __shfl_xor_sync(0xffffffffu, m, off));
            float s = 0.0f;
            for (int j = lane; j < ncols; j += 32) {
                float e = __expf(prow[j] - m);
                prow[j] = e;
                s += e;
            }
#pragma unroll
            for (int off = 16; off > 0; off >>= 1)
                s += __shfl_xor_sync(0xffffffffu, s, off);
            float inv = 1.0f / s;
            for (int j = lane; j < ncols; j += 32) prow[j] *= inv;
        }
    }
    __syncthreads();

    float accO[4][4];
#pragma unroll
    for (int r = 0; r < 4; r++)
#pragma unroll
        for (int d = 0; d < 4; d++) accO[r][d] = 0.0f;

#pragma unroll 2
    for (int j = 0; j < ncols; j++) {
        float p[4], v[4];
#pragma unroll
        for (int r = 0; r < 4; r++) p[r] = sP[(ty + 16 * r) * 257 + j];
#pragma unroll
        for (int d = 0; d < 4; d++) v[d] = sV[j * 64 + tx + 16 * d];
#pragma unroll
        for (int r = 0; r < 4; r++)
#pragma unroll
            for (int d = 0; d < 4; d++)
                accO[r][d] = fmaf(p[r], v[d], accO[r][d]);
    }

#pragma unroll
    for (int r = 0; r < 4; r++) {
        size_t base = (brow + r0 + ty + 16 * r) * (size_t)HEAD;
#pragma unroll
        for (int d = 0; d < 4; d++)
            out[base + tx + 16 * d] = accO[r][d];
    }
}

// ---------------------------------------------------------------------------
extern "C" void kernel_launch(void* const* d_in, const int* in_sizes, int n_in,
                              void* d_out, int out_size)
{
    const float* x  = (const float*)d_in[0];
    const float* Wq = (const float*)d_in[1];
    const float* Wk = (const float*)d_in[2];
    const float* Wv = (const float*)d_in[3];
    float* out = (float*)d_out;

    (void)in_sizes; (void)n_in; (void)out_size;

    cudaFuncSetAttribute(qkv_mma_kernel,
                         cudaFuncAttributeMaxDynamicSharedMemorySize,
                         QKV_SMEM_BYTES);
    cudaFuncSetAttribute(attn_kernel,
                         cudaFuncAttributeMaxDynamicSharedMemorySize,
                         (int)ATTN_SMEM_BYTES);

    xprep_kernel<<<MROWS * CEMB / 4 / 256, 256>>>(x);
    wprep_kernel<<<(NQKV * CEMB + 255) / 256, 256>>>(Wq, Wk, Wv);
    qkv_mma_kernel<<<MROWS / 128, 256, QKV_SMEM_BYTES>>>();
    attn_kernel<<<dim3(4, BATCH), 256, ATTN_SMEM_BYTES>>>(out);
}

// round 6
// speedup vs baseline: 3.5048x; 1.2580x over previous
#include <cuda_runtime.h>
#include <cuda_bf16.h>
#include <cstdint>

// Problem constants
#define BATCH 512
#define SEQ   256
#define CEMB  384
#define HEAD  64
#define MROWS (BATCH * SEQ)          // 131072
#define NQKV  (3 * HEAD)             // 192
#define SCALE 0.05103103630798288f   // 384^-0.5

// Scratch buffers
__device__ __nv_bfloat16 g_Xhi[(size_t)MROWS * CEMB];
__device__ __nv_bfloat16 g_Xlo[(size_t)MROWS * CEMB];
__device__ __nv_bfloat16 g_WThi[NQKV * CEMB];
__device__ __nv_bfloat16 g_WTlo[NQKV * CEMB];
// Split QKV outputs (Q pre-scaled by SCALE)
__device__ __nv_bfloat16 g_Qhi[(size_t)MROWS * HEAD];
__device__ __nv_bfloat16 g_Qlo[(size_t)MROWS * HEAD];
__device__ __nv_bfloat16 g_Khi[(size_t)MROWS * HEAD];
__device__ __nv_bfloat16 g_Klo[(size_t)MROWS * HEAD];
__device__ __nv_bfloat16 g_Vhi[(size_t)MROWS * HEAD];
__device__ __nv_bfloat16 g_Vlo[(size_t)MROWS * HEAD];

// ---------------------------------------------------------------------------
// Warp-MMA helpers (baseline PTX, legal on .target sm_103)
// ---------------------------------------------------------------------------
__device__ __forceinline__ uint32_t smem_to_u32(const void* p) {
    uint32_t a;
    asm("{ .reg .u64 t; cvta.to.shared.u64 t, %1; cvt.u32.u64 %0, t; }"
        : "=r"(a) : "l"(p));
    return a;
}

#define LDSM_X4(r0, r1, r2, r3, addr) \
    asm volatile("ldmatrix.sync.aligned.m8n8.x4.shared.b16 {%0,%1,%2,%3}, [%4];" \
        : "=r"(r0), "=r"(r1), "=r"(r2), "=r"(r3) : "r"(addr))

#define LDSM_X4_T(r0, r1, r2, r3, addr) \
    asm volatile("ldmatrix.sync.aligned.m8n8.x4.trans.shared.b16 {%0,%1,%2,%3}, [%4];" \
        : "=r"(r0), "=r"(r1), "=r"(r2), "=r"(r3) : "r"(addr))

#define MMA16816(d, a, b0, b1) \
    asm volatile("mma.sync.aligned.m16n8k16.row.col.f32.bf16.bf16.f32 " \
        "{%0,%1,%2,%3}, {%4,%5,%6,%7}, {%8,%9}, {%0,%1,%2,%3};" \
        : "+f"((d)[0]), "+f"((d)[1]), "+f"((d)[2]), "+f"((d)[3]) \
        : "r"((a)[0]), "r"((a)[1]), "r"((a)[2]), "r"((a)[3]), \
          "r"(b0), "r"(b1))

// ---------------------------------------------------------------------------
// Prep kernels
// ---------------------------------------------------------------------------
__global__ __launch_bounds__(256) void xprep_kernel(const float* __restrict__ x)
{
    size_t i = (size_t)blockIdx.x * 256 + threadIdx.x;
    float4 v = ((const float4*)x)[i];
    __nv_bfloat16 h0 = __float2bfloat16(v.x);
    __nv_bfloat16 h1 = __float2bfloat16(v.y);
    __nv_bfloat16 h2 = __float2bfloat16(v.z);
    __nv_bfloat16 h3 = __float2bfloat16(v.w);
    __nv_bfloat16 l0 = __float2bfloat16(v.x - __bfloat162float(h0));
    __nv_bfloat16 l1 = __float2bfloat16(v.y - __bfloat162float(h1));
    __nv_bfloat16 l2 = __float2bfloat16(v.z - __bfloat162float(h2));
    __nv_bfloat16 l3 = __float2bfloat16(v.w - __bfloat162float(h3));
    __nv_bfloat162 hp0 = __halves2bfloat162(h0, h1);
    __nv_bfloat162 hp1 = __halves2bfloat162(h2, h3);
    __nv_bfloat162 lp0 = __halves2bfloat162(l0, l1);
    __nv_bfloat162 lp1 = __halves2bfloat162(l2, l3);
    uint2 hw, lw;
    hw.x = *(uint32_t*)&hp0;  hw.y = *(uint32_t*)&hp1;
    lw.x = *(uint32_t*)&lp0;  lw.y = *(uint32_t*)&lp1;
    ((uint2*)g_Xhi)[i] = hw;
    ((uint2*)g_Xlo)[i] = lw;
}

__global__ void wprep_kernel(const float* __restrict__ Wq,
                             const float* __restrict__ Wk,
                             const float* __restrict__ Wv)
{
    int idx = blockIdx.x * 256 + threadIdx.x;
    if (idx >= NQKV * CEMB) return;
    int n = idx / CEMB, k = idx % CEMB;
    int mat = n >> 6, h = n & 63;
    const float* W = (mat == 0) ? Wq : (mat == 1) ? Wk : Wv;
    float v = W[k * HEAD + h];
    __nv_bfloat16 hi = __float2bfloat16(v);
    g_WThi[idx] = hi;
    g_WTlo[idx] = __float2bfloat16(v - __bfloat162float(hi));
}

// ---------------------------------------------------------------------------
// QKV projection via HMMA, bf16 split-accumulate.
// BM=128, BN=192, BK=32, 256 threads; warps 4(M) x 2(N).
// Epilogue emits split bf16 Q (pre-scaled), K, V.
// ---------------------------------------------------------------------------
#define QPAD 40
#define SOFF_AHI 0
#define SOFF_ALO (128 * QPAD)
#define SOFF_BHI (2 * 128 * QPAD)
#define SOFF_BLO (2 * 128 * QPAD + 192 * QPAD)
#define QKV_SMEM_BYTES ((2 * 128 * QPAD + 2 * 192 * QPAD) * 2)

__global__ __launch_bounds__(256) void qkv_mma_kernel()
{
    extern __shared__ __nv_bfloat16 smq[];
    const uint32_t sbase = smem_to_u32(smq);
    const int tid   = threadIdx.x;
    const int lane  = tid & 31;
    const int wid   = tid >> 5;
    const int warpM = wid & 3;
    const int warpN = wid >> 2;
    const int row0  = blockIdx.x * 128;

    const int laneRow = lane & 15;
    const int laneK   = (lane >> 4) << 3;

    float acc[2][12][4];
#pragma unroll
    for (int mt = 0; mt < 2; mt++)
#pragma unroll
        for (int nt = 0; nt < 12; nt++)
#pragma unroll
            for (int e = 0; e < 4; e++) acc[mt][nt][e] = 0.0f;

    for (int chunk = 0; chunk < 12; chunk++) {
        const int k0 = chunk * 32;
#pragma unroll
        for (int i = 0; i < 4; i++) {
            int li = tid + i * 256;
            int r = li >> 3, g = li & 7;
            size_t src = ((size_t)(row0 + r) * CEMB + k0 + g * 4);
            uint2 hv = *(const uint2*)&g_Xhi[src];
            uint2 lv = *(const uint2*)&g_Xlo[src];
            *(uint2*)&smq[SOFF_AHI + r * QPAD + g * 4] = hv;
            *(uint2*)&smq[SOFF_ALO + r * QPAD + g * 4] = lv;
        }
#pragma unroll
        for (int i = 0; i < 6; i++) {
            int li = tid + i * 256;
            int r = li >> 3, g = li & 7;
            size_t src = ((size_t)r * CEMB + k0 + g * 4);
            uint2 hv = *(const uint2*)&g_WThi[src];
            uint2 lv = *(const uint2*)&g_WTlo[src];
            *(uint2*)&smq[SOFF_BHI + r * QPAD + g * 4] = hv;
            *(uint2*)&smq[SOFF_BLO + r * QPAD + g * 4] = lv;
        }
        __syncthreads();

#pragma unroll
        for (int ks = 0; ks < 2; ks++) {
            const int kk = ks * 16 + laneK;
            uint32_t ahi[2][4], alo[2][4];
#pragma unroll
            for (int mt = 0; mt < 2; mt++) {
                uint32_t off = (uint32_t)((warpM * 32 + mt * 16 + laneRow) * QPAD + kk) * 2;
                LDSM_X4(ahi[mt][0], ahi[mt][1], ahi[mt][2], ahi[mt][3],
                        sbase + SOFF_AHI * 2 + off);
                LDSM_X4(alo[mt][0], alo[mt][1], alo[mt][2], alo[mt][3],
                        sbase + SOFF_ALO * 2 + off);
            }
#pragma unroll
            for (int p = 0; p < 3; p++) {
                const uint32_t bOffBase = (p == 1) ? (uint32_t)(SOFF_BLO * 2)
                                                   : (uint32_t)(SOFF_BHI * 2);
                uint32_t (*A)[4] = (p < 2) ? ahi : alo;
                uint32_t bf[6][4];
#pragma unroll
                for (int j = 0; j < 6; j++) {
                    uint32_t off = (uint32_t)((warpN * 96 + j * 16 + laneRow) * QPAD + kk) * 2;
                    LDSM_X4(bf[j][0], bf[j][1], bf[j][2], bf[j][3],
                            sbase + bOffBase + off);
                }
#pragma unroll
                for (int mt = 0; mt < 2; mt++)
#pragma unroll
                    for (int j = 0; j < 6; j++) {
                        MMA16816(acc[mt][2 * j],     A[mt], bf[j][0], bf[j][2]);
                        MMA16816(acc[mt][2 * j + 1], A[mt], bf[j][1], bf[j][3]);
                    }
            }
        }
        __syncthreads();
    }

    // Epilogue: split to bf16 hi/lo, route to Q (scaled) / K / V
    const int qrow = lane >> 2;
    const int qcol = (lane & 3) * 2;
#pragma unroll
    for (int mt = 0; mt < 2; mt++) {
#pragma unroll
        for (int h = 0; h < 2; h++) {
            int row = row0 + warpM * 32 + mt * 16 + qrow + 8 * h;
#pragma unroll
            for (int j = 0; j < 12; j++) {
                int n = warpN * 96 + j * 8 + qcol;
                int mat = n >> 6;            // 0=Q 1=K 2=V
                int cc  = n & 63;
                float v0 = acc[mt][j][2 * h];
                float v1 = acc[mt][j][2 * h + 1];
                if (mat == 0) { v0 *= SCALE; v1 *= SCALE; }
                __nv_bfloat16 h0 = __float2bfloat16(v0);
                __nv_bfloat16 h1 = __float2bfloat16(v1);
                __nv_bfloat16 l0 = __float2bfloat16(v0 - __bfloat162float(h0));
                __nv_bfloat16 l1 = __float2bfloat16(v1 - __bfloat162float(h1));
                __nv_bfloat16* bhi = (mat == 0) ? g_Qhi : (mat == 1) ? g_Khi : g_Vhi;
                __nv_bfloat16* blo = (mat == 0) ? g_Qlo : (mat == 1) ? g_Klo : g_Vlo;
                size_t o = (size_t)row * HEAD + cc;
                *(__nv_bfloat162*)&bhi[o] = __halves2bfloat162(h0, h1);
                *(__nv_bfloat162*)&blo[o] = __halves2bfloat162(l0, l1);
            }
        }
    }
}

// ---------------------------------------------------------------------------
// Attention via HMMA. Block = (row-tile 64, batch). 256 threads, 8 warps:
// warpM = wid&1 (rows 32), warpN = wid>>1 (16 score-cols / head-dims).
// Stage 1: S = Q K^T (3-pass split) -> fp32 smem strip
// Stage 2: softmax (fp32, exact as before)
// Stage 3: O = P V (P split on the fly, V via ldmatrix.trans)
// ---------------------------------------------------------------------------
#define AST 72                      // bf16 row stride for MMA tiles
#define SST 258                     // fp32 score-row stride (even -> 8B aligned)
#define TBUF (64 * AST)             // 4608 bf16 = 9216 B per tile buffer
#define ATTN_SMEM_BYTES (6 * TBUF * 2 + 64 * SST * 4)   // 121344

__global__ __launch_bounds__(256) void attn_mma_kernel(float* __restrict__ out)
{
    extern __shared__ char sm[];
    __nv_bfloat16* sbf = (__nv_bfloat16*)sm;
    // buffer order: Qh, Ql, KVh, KVl, Ph, Pl
    float* sS = (float*)(sm + 6 * TBUF * 2);
    const uint32_t sb = smem_to_u32(sm);
    const uint32_t oQh = 0, oQl = TBUF * 2, oKh = 2 * TBUF * 2, oKl = 3 * TBUF * 2;
    const uint32_t oPh = 4 * TBUF * 2, oPl = 5 * TBUF * 2;

    const int tid = threadIdx.x, lane = tid & 31, wid = tid >> 5;
    const int warpM = wid & 1, warpN = wid >> 1;
    const int rt = blockIdx.x, batch = blockIdx.y;
    const int r0 = rt * 64;
    const size_t brow = (size_t)batch * SEQ;
    const int laneRow = lane & 15, laneK8 = (lane >> 4) << 3;
    const int qrow = lane >> 2, qcol = (lane & 3) * 2;

    // Load Q tile (rows r0..r0+63): 512 uint4 per buffer, 2/thread
#pragma unroll
    for (int i = 0; i < 2; i++) {
        int li = tid + i * 256;
        int r = li >> 3, g = li & 7;
        size_t src = (brow + r0 + r) * HEAD + g * 8;
        *(uint4*)&sbf[0 * TBUF + r * AST + g * 8] = *(const uint4*)&g_Qhi[src];
        *(uint4*)&sbf[1 * TBUF + r * AST + g * 8] = *(const uint4*)&g_Qlo[src];
    }

    // ---- Stage 1: scores ----
    for (int kc = 0; kc <= rt; kc++) {
        __syncthreads();
#pragma unroll
        for (int i = 0; i < 2; i++) {
            int li = tid + i * 256;
            int r = li >> 3, g = li & 7;
            size_t src = (brow + kc * 64 + r) * HEAD + g * 8;
            *(uint4*)&sbf[2 * TBUF + r * AST + g * 8] = *(const uint4*)&g_Khi[src];
            *(uint4*)&sbf[3 * TBUF + r * AST + g * 8] = *(const uint4*)&g_Klo[src];
        }
        __syncthreads();

        float accS[2][2][4];
#pragma unroll
        for (int mt = 0; mt < 2; mt++)
#pragma unroll
            for (int j = 0; j < 2; j++)
#pragma unroll
                for (int e = 0; e < 4; e++) accS[mt][j][e] = 0.0f;

#pragma unroll
        for (int ks = 0; ks < 4; ks++) {
            const int kk = ks * 16 + laneK8;
            uint32_t ah[2][4], al[2][4];
#pragma unroll
            for (int mt = 0; mt < 2; mt++) {
                uint32_t off = (uint32_t)((warpM * 32 + mt * 16 + laneRow) * AST + kk) * 2;
                LDSM_X4(ah[mt][0], ah[mt][1], ah[mt][2], ah[mt][3], sb + oQh + off);
                LDSM_X4(al[mt][0], al[mt][1], al[mt][2], al[mt][3], sb + oQl + off);
            }
            uint32_t bh[4], bl[4];
            uint32_t offB = (uint32_t)((warpN * 16 + laneRow) * AST + kk) * 2;
            LDSM_X4(bh[0], bh[1], bh[2], bh[3], sb + oKh + offB);
            LDSM_X4(bl[0], bl[1], bl[2], bl[3], sb + oKl + offB);
#pragma unroll
            for (int mt = 0; mt < 2; mt++) {
                MMA16816(accS[mt][0], ah[mt], bh[0], bh[2]);
                MMA16816(accS[mt][1], ah[mt], bh[1], bh[3]);
                MMA16816(accS[mt][0], ah[mt], bl[0], bl[2]);
                MMA16816(accS[mt][1], ah[mt], bl[1], bl[3]);
                MMA16816(accS[mt][0], al[mt], bh[0], bh[2]);
                MMA16816(accS[mt][1], al[mt], bh[1], bh[3]);
            }
        }
        // write masked scores
#pragma unroll
        for (int mt = 0; mt < 2; mt++)
#pragma unroll
            for (int h = 0; h < 2; h++) {
                int row = warpM * 32 + mt * 16 + qrow + 8 * h;
                int gi = r0 + row;
#pragma unroll
                for (int j = 0; j < 2; j++) {
                    int col = kc * 64 + warpN * 16 + j * 8 + qcol;
                    float f0 = (col     <= gi) ? accS[mt][j][2 * h]     : -1e30f;
                    float f1 = (col + 1 <= gi) ? accS[mt][j][2 * h + 1] : -1e30f;
                    *(float2*)&sS[row * SST + col] = make_float2(f0, f1);
                }
            }
    }
    __syncthreads();

    // ---- Stage 2: softmax ----
    {
        const int ncols = (rt + 1) * 64;
        for (int rr = 0; rr < 8; rr++) {
            int row = wid * 8 + rr;
            float* prow = sS + row * SST;
            float m = -1e30f;
            for (int j = lane; j < ncols; j += 32) m = fmaxf(m, prow[j]);
#pragma unroll
            for (int off = 16; off > 0; off >>= 1)
                m = fmaxf(m, __shfl_xor_sync(0xffffffffu, m, off));
            float s = 0.0f;
            for (int j = lane; j < ncols; j += 32) {
                float e = __expf(prow[j] - m);
                prow[j] = e;
                s += e;
            }
#pragma unroll
            for (int off = 16; off > 0; off >>= 1)
                s += __shfl_xor_sync(0xffffffffu, s, off);
            float inv = 1.0f / s;
            for (int j = lane; j < ncols; j += 32) prow[j] *= inv;
        }
    }

    // ---- Stage 3: O = P V ----
    float accO[2][2][4];
#pragma unroll
    for (int mt = 0; mt < 2; mt++)
#pragma unroll
        for (int j = 0; j < 2; j++)
#pragma unroll
            for (int e = 0; e < 4; e++) accO[mt][j][e] = 0.0f;

    for (int kc = 0; kc <= rt; kc++) {
        __syncthreads();
        // V chunk
#pragma unroll
        for (int i = 0; i < 2; i++) {
            int li = tid + i * 256;
            int r = li >> 3, g = li & 7;
            size_t src = (brow + kc * 64 + r) * HEAD + g * 8;
            *(uint4*)&sbf[2 * TBUF + r * AST + g * 8] = *(const uint4*)&g_Vhi[src];
            *(uint4*)&sbf[3 * TBUF + r * AST + g * 8] = *(const uint4*)&g_Vlo[src];
        }
        // P chunk -> bf16 hi/lo
#pragma unroll
        for (int i = 0; i < 16; i++) {
            int li = tid + i * 256;
            int r = li >> 6, c = li & 63;
            float p = sS[r * SST + kc * 64 + c];
            __nv_bfloat16 ph = __float2bfloat16(p);
            sbf[4 * TBUF + r * AST + c] = ph;
            sbf[5 * TBUF + r * AST + c] = __float2bfloat16(p - __bfloat162float(ph));
        }
        __syncthreads();

#pragma unroll
        for (int ks = 0; ks < 4; ks++) {
            const int kk = ks * 16 + laneK8;
            uint32_t ah[2][4], al[2][4];
#pragma unroll
            for (int mt = 0; mt < 2; mt++) {
                uint32_t off = (uint32_t)((warpM * 32 + mt * 16 + laneRow) * AST + kk) * 2;
                LDSM_X4(ah[mt][0], ah[mt][1], ah[mt][2], ah[mt][3], sb + oPh + off);
                LDSM_X4(al[mt][0], al[mt][1], al[mt][2], al[mt][3], sb + oPl + off);
            }
            // trans-ldmatrix B from V[s][d]
            int kRow = ks * 16 + (lane & 7) + ((lane >> 4) << 3);
            int nCol = warpN * 16 + ((lane >> 3) & 1) * 8;
            uint32_t offV = (uint32_t)(kRow * AST + nCol) * 2;
            uint32_t bh[4], bl[4];
            LDSM_X4_T(bh[0], bh[1], bh[2], bh[3], sb + oKh + offV);
            LDSM_X4_T(bl[0], bl[1], bl[2], bl[3], sb + oKl + offV);
#pragma unroll
            for (int mt = 0; mt < 2; mt++) {
                MMA16816(accO[mt][0], ah[mt], bh[0], bh[2]);
                MMA16816(accO[mt][1], ah[mt], bh[1], bh[3]);
                MMA16816(accO[mt][0], ah[mt], bl[0], bl[2]);
                MMA16816(accO[mt][1], ah[mt], bl[1], bl[3]);
                MMA16816(accO[mt][0], al[mt], bh[0], bh[2]);
                MMA16816(accO[mt][1], al[mt], bh[1], bh[3]);
            }
        }
    }

    // write O
#pragma unroll
    for (int mt = 0; mt < 2; mt++)
#pragma unroll
        for (int h = 0; h < 2; h++) {
            int row = warpM * 32 + mt * 16 + qrow + 8 * h;
            size_t base = (brow + r0 + row) * (size_t)HEAD;
#pragma unroll
            for (int j = 0; j < 2; j++) {
                int col = warpN * 16 + j * 8 + qcol;
                *(float2*)&out[base + col] =
                    make_float2(accO[mt][j][2 * h], accO[mt][j][2 * h + 1]);
            }
        }
}

// ---------------------------------------------------------------------------
extern "C" void kernel_launch(void* const* d_in, const int* in_sizes, int n_in,
                              void* d_out, int out_size)
{
    const float* x  = (const float*)d_in[0];
    const float* Wq = (const float*)d_in[1];
    const float* Wk = (const float*)d_in[2];
    const float* Wv = (const float*)d_in[3];
    float* out = (float*)d_out;

    (void)in_sizes; (void)n_in; (void)out_size;

    cudaFuncSetAttribute(qkv_mma_kernel,
                         cudaFuncAttributeMaxDynamicSharedMemorySize,
                         QKV_SMEM_BYTES);
    cudaFuncSetAttribute(attn_mma_kernel,
                         cudaFuncAttributeMaxDynamicSharedMemorySize,
                         ATTN_SMEM_BYTES);

    xprep_kernel<<<MROWS * CEMB / 4 / 256, 256>>>(x);
    wprep_kernel<<<(NQKV * CEMB + 255) / 256, 256>>>(Wq, Wk, Wv);
    qkv_mma_kernel<<<MROWS / 128, 256, QKV_SMEM_BYTES>>>();
    attn_mma_kernel<<<dim3(4, BATCH), 256, ATTN_SMEM_BYTES>>>(out);
}

// round 7
// speedup vs baseline: 5.0552x; 1.4424x over previous
#include <cuda_runtime.h>
#include <cuda_bf16.h>
#include <cstdint>

// Problem constants
#define BATCH 512
#define SEQ   256
#define CEMB  384
#define HEAD  64
#define MROWS (BATCH * SEQ)          // 131072
#define NQKV  (3 * HEAD)             // 192
#define SCALE 0.05103103630798288f   // 384^-0.5

// Scratch buffers
__device__ __nv_bfloat16 g_WThi[NQKV * CEMB];
__device__ __nv_bfloat16 g_WTlo[NQKV * CEMB];
__device__ __nv_bfloat16 g_Qhi[(size_t)MROWS * HEAD];   // Q pre-scaled
__device__ __nv_bfloat16 g_Qlo[(size_t)MROWS * HEAD];
__device__ __nv_bfloat16 g_Khi[(size_t)MROWS * HEAD];
__device__ __nv_bfloat16 g_Klo[(size_t)MROWS * HEAD];
__device__ __nv_bfloat16 g_Vhi[(size_t)MROWS * HEAD];
__device__ __nv_bfloat16 g_Vlo[(size_t)MROWS * HEAD];

// ---------------------------------------------------------------------------
// Warp-MMA helpers (baseline PTX, legal on .target sm_103)
// ---------------------------------------------------------------------------
__device__ __forceinline__ uint32_t smem_to_u32(const void* p) {
    uint32_t a;
    asm("{ .reg .u64 t; cvta.to.shared.u64 t, %1; cvt.u32.u64 %0, t; }"
        : "=r"(a) : "l"(p));
    return a;
}

#define LDSM_X4(r0, r1, r2, r3, addr) \
    asm volatile("ldmatrix.sync.aligned.m8n8.x4.shared.b16 {%0,%1,%2,%3}, [%4];" \
        : "=r"(r0), "=r"(r1), "=r"(r2), "=r"(r3) : "r"(addr))

#define LDSM_X4_T(r0, r1, r2, r3, addr) \
    asm volatile("ldmatrix.sync.aligned.m8n8.x4.trans.shared.b16 {%0,%1,%2,%3}, [%4];" \
        : "=r"(r0), "=r"(r1), "=r"(r2), "=r"(r3) : "r"(addr))

#define MMA16816(d, a, b0, b1) \
    asm volatile("mma.sync.aligned.m16n8k16.row.col.f32.bf16.bf16.f32 " \
        "{%0,%1,%2,%3}, {%4,%5,%6,%7}, {%8,%9}, {%0,%1,%2,%3};" \
        : "+f"((d)[0]), "+f"((d)[1]), "+f"((d)[2]), "+f"((d)[3]) \
        : "r"((a)[0]), "r"((a)[1]), "r"((a)[2]), "r"((a)[3]), \
          "r"(b0), "r"(b1))

// fp32 pair -> bf16 hi/lo packed pairs
__device__ __forceinline__ void split2(float a, float b, uint32_t& hi, uint32_t& lo) {
    __nv_bfloat16 ha = __float2bfloat16(a);
    __nv_bfloat16 hb = __float2bfloat16(b);
    __nv_bfloat16 la = __float2bfloat16(a - __bfloat162float(ha));
    __nv_bfloat16 lb = __float2bfloat16(b - __bfloat162float(hb));
    __nv_bfloat162 hp = __halves2bfloat162(ha, hb);
    __nv_bfloat162 lp = __halves2bfloat162(la, lb);
    hi = *(uint32_t*)&hp;
    lo = *(uint32_t*)&lp;
}

// ---------------------------------------------------------------------------
// Prep: W^T + bf16 hi/lo split.  g_WT[n][k] = W[k][n], n = mat*64 + h
// ---------------------------------------------------------------------------
__global__ void wprep_kernel(const float* __restrict__ Wq,
                             const float* __restrict__ Wk,
                             const float* __restrict__ Wv)
{
    int idx = blockIdx.x * 256 + threadIdx.x;
    if (idx >= NQKV * CEMB) return;
    int n = idx / CEMB, k = idx % CEMB;
    int mat = n >> 6, h = n & 63;
    const float* W = (mat == 0) ? Wq : (mat == 1) ? Wk : Wv;
    float v = W[k * HEAD + h];
    __nv_bfloat16 hi = __float2bfloat16(v);
    g_WThi[idx] = hi;
    g_WTlo[idx] = __float2bfloat16(v - __bfloat162float(hi));
}

// ---------------------------------------------------------------------------
// QKV projection via HMMA, bf16 split-accumulate. x split done inline.
// BM=128, BN=192, BK=32, 256 threads; warps 4(M) x 2(N).
// ---------------------------------------------------------------------------
#define QPAD 40
#define SOFF_AHI 0
#define SOFF_ALO (128 * QPAD)
#define SOFF_BHI (2 * 128 * QPAD)
#define SOFF_BLO (2 * 128 * QPAD + 192 * QPAD)
#define QKV_SMEM_BYTES ((2 * 128 * QPAD + 2 * 192 * QPAD) * 2)

__global__ __launch_bounds__(256) void qkv_mma_kernel(const float* __restrict__ x)
{
    extern __shared__ __nv_bfloat16 smq[];
    const uint32_t sbase = smem_to_u32(smq);
    const int tid   = threadIdx.x;
    const int lane  = tid & 31;
    const int wid   = tid >> 5;
    const int warpM = wid & 3;
    const int warpN = wid >> 2;
    const int row0  = blockIdx.x * 128;

    const int laneRow = lane & 15;
    const int laneK   = (lane >> 4) << 3;

    float acc[2][12][4];
#pragma unroll
    for (int mt = 0; mt < 2; mt++)
#pragma unroll
        for (int nt = 0; nt < 12; nt++)
#pragma unroll
            for (int e = 0; e < 4; e++) acc[mt][nt][e] = 0.0f;

    for (int chunk = 0; chunk < 12; chunk++) {
        const int k0 = chunk * 32;
        // A tile: load x fp32, split hi/lo inline. 128 rows x 4 groups of 8.
#pragma unroll
        for (int i = 0; i < 2; i++) {
            int li = tid + i * 256;
            int r = li >> 2, g = li & 3;
            const float4* src = (const float4*)&x[(size_t)(row0 + r) * CEMB + k0 + g * 8];
            float4 v0 = src[0], v1 = src[1];
            uint4 hw, lw;
            split2(v0.x, v0.y, hw.x, lw.x);
            split2(v0.z, v0.w, hw.y, lw.y);
            split2(v1.x, v1.y, hw.z, lw.z);
            split2(v1.z, v1.w, hw.w, lw.w);
            *(uint4*)&smq[SOFF_AHI + r * QPAD + g * 8] = hw;
            *(uint4*)&smq[SOFF_ALO + r * QPAD + g * 8] = lw;
        }
        // B tiles: pre-split W^T
#pragma unroll
        for (int i = 0; i < 6; i++) {
            int li = tid + i * 256;
            int r = li >> 3, g = li & 7;
            size_t src = ((size_t)r * CEMB + k0 + g * 4);
            uint2 hv = *(const uint2*)&g_WThi[src];
            uint2 lv = *(const uint2*)&g_WTlo[src];
            *(uint2*)&smq[SOFF_BHI + r * QPAD + g * 4] = hv;
            *(uint2*)&smq[SOFF_BLO + r * QPAD + g * 4] = lv;
        }
        __syncthreads();

#pragma unroll
        for (int ks = 0; ks < 2; ks++) {
            const int kk = ks * 16 + laneK;
            uint32_t ahi[2][4], alo[2][4];
#pragma unroll
            for (int mt = 0; mt < 2; mt++) {
                uint32_t off = (uint32_t)((warpM * 32 + mt * 16 + laneRow) * QPAD + kk) * 2;
                LDSM_X4(ahi[mt][0], ahi[mt][1], ahi[mt][2], ahi[mt][3],
                        sbase + SOFF_AHI * 2 + off);
                LDSM_X4(alo[mt][0], alo[mt][1], alo[mt][2], alo[mt][3],
                        sbase + SOFF_ALO * 2 + off);
            }
#pragma unroll
            for (int p = 0; p < 3; p++) {
                const uint32_t bOffBase = (p == 1) ? (uint32_t)(SOFF_BLO * 2)
                                                   : (uint32_t)(SOFF_BHI * 2);
                uint32_t (*A)[4] = (p < 2) ? ahi : alo;
                uint32_t bf[6][4];
#pragma unroll
                for (int j = 0; j < 6; j++) {
                    uint32_t off = (uint32_t)((warpN * 96 + j * 16 + laneRow) * QPAD + kk) * 2;
                    LDSM_X4(bf[j][0], bf[j][1], bf[j][2], bf[j][3],
                            sbase + bOffBase + off);
                }
#pragma unroll
                for (int mt = 0; mt < 2; mt++)
#pragma unroll
                    for (int j = 0; j < 6; j++) {
                        MMA16816(acc[mt][2 * j],     A[mt], bf[j][0], bf[j][2]);
                        MMA16816(acc[mt][2 * j + 1], A[mt], bf[j][1], bf[j][3]);
                    }
            }
        }
        __syncthreads();
    }

    // Epilogue: split to bf16 hi/lo, route to Q (scaled) / K / V
    const int qrow = lane >> 2;
    const int qcol = (lane & 3) * 2;
#pragma unroll
    for (int mt = 0; mt < 2; mt++) {
#pragma unroll
        for (int h = 0; h < 2; h++) {
            int row = row0 + warpM * 32 + mt * 16 + qrow + 8 * h;
#pragma unroll
            for (int j = 0; j < 12; j++) {
                int n = warpN * 96 + j * 8 + qcol;
                int mat = n >> 6;
                int cc  = n & 63;
                float v0 = acc[mt][j][2 * h];
                float v1 = acc[mt][j][2 * h + 1];
                if (mat == 0) { v0 *= SCALE; v1 *= SCALE; }
                uint32_t hp, lp;
                split2(v0, v1, hp, lp);
                __nv_bfloat16* bhi = (mat == 0) ? g_Qhi : (mat == 1) ? g_Khi : g_Vhi;
                __nv_bfloat16* blo = (mat == 0) ? g_Qlo : (mat == 1) ? g_Klo : g_Vlo;
                size_t o = (size_t)row * HEAD + cc;
                *(uint32_t*)&bhi[o] = hp;
                *(uint32_t*)&blo[o] = lp;
            }
        }
    }
}

// ---------------------------------------------------------------------------
// Flash-attention-2 style attention.
// Block = (128-row tile rt in {0,1}, batch). 256 threads, 8 warps x 16 rows.
// Online softmax; P stays in registers (S C-frag == PV A-frag identity).
// smem: Q hi/lo (128x64) + K,V hi/lo chunk (64x64) = 73728 B -> 2 blocks/SM.
// ---------------------------------------------------------------------------
#define FST 72
#define OQH 0
#define OQL (128 * FST * 2)
#define OKH (2 * 128 * FST * 2)
#define OKL (OKH + 64 * FST * 2)
#define OVH (OKL + 64 * FST * 2)
#define OVL (OVH + 64 * FST * 2)
#define FLASH_SMEM_BYTES (OVL + 64 * FST * 2)   // 73728

__global__ __launch_bounds__(256, 2) void flash_kernel(float* __restrict__ out)
{
    extern __shared__ char sm[];
    __nv_bfloat16* sbf = (__nv_bfloat16*)sm;
    const uint32_t sb = smem_to_u32(sm);
    const int tid = threadIdx.x, lane = tid & 31, wid = tid >> 5;
    const int rt = blockIdx.x, batch = blockIdx.y;
    const int r0 = rt * 128;
    const size_t brow = (size_t)batch * SEQ;
    const int qrow = lane >> 2, qcol = (lane & 3) * 2;
    const int laneRow = lane & 15, laneK8 = (lane >> 4) << 3;

    // Load Q tile (128 rows, hi/lo)
#pragma unroll
    for (int i = 0; i < 4; i++) {
        int li = tid + i * 256;
        int r = li >> 3, g = li & 7;
        size_t src = (brow + r0 + r) * HEAD + g * 8;
        *(uint4*)&sbf[OQH / 2 + r * FST + g * 8] = *(const uint4*)&g_Qhi[src];
        *(uint4*)&sbf[OQL / 2 + r * FST + g * 8] = *(const uint4*)&g_Qlo[src];
    }
    __syncthreads();

    // Hoist Q-hi fragments (loop-invariant)
    uint32_t qh[4][4];
#pragma unroll
    for (int ks = 0; ks < 4; ks++) {
        uint32_t off = (uint32_t)((wid * 16 + laneRow) * FST + ks * 16 + laneK8) * 2;
        LDSM_X4(qh[ks][0], qh[ks][1], qh[ks][2], qh[ks][3], sb + OQH + off);
    }

    float accO[8][4];
#pragma unroll
    for (int n = 0; n < 8; n++)
#pragma unroll
        for (int e = 0; e < 4; e++) accO[n][e] = 0.0f;
    float m0 = -1e30f, m1 = -1e30f, l0 = 0.0f, l1 = 0.0f;

    const int nch = 2 * (rt + 1);
    for (int kc = 0; kc < nch; kc++) {
        __syncthreads();
        // Load K,V chunk (64 rows, hi/lo)
#pragma unroll
        for (int i = 0; i < 2; i++) {
            int li = tid + i * 256;
            int r = li >> 3, g = li & 7;
            size_t src = (brow + kc * 64 + r) * HEAD + g * 8;
            *(uint4*)&sbf[OKH / 2 + r * FST + g * 8] = *(const uint4*)&g_Khi[src];
            *(uint4*)&sbf[OKL / 2 + r * FST + g * 8] = *(const uint4*)&g_Klo[src];
            *(uint4*)&sbf[OVH / 2 + r * FST + g * 8] = *(const uint4*)&g_Vhi[src];
            *(uint4*)&sbf[OVL / 2 + r * FST + g * 8] = *(const uint4*)&g_Vlo[src];
        }
        __syncthreads();

        // ---- S = Q K^T (3-pass split) ----
        float accS[8][4];
#pragma unroll
        for (int n = 0; n < 8; n++)
#pragma unroll
            for (int e = 0; e < 4; e++) accS[n][e] = 0.0f;

#pragma unroll
        for (int ks = 0; ks < 4; ks++) {
            uint32_t ql[4];
            uint32_t offQ = (uint32_t)((wid * 16 + laneRow) * FST + ks * 16 + laneK8) * 2;
            LDSM_X4(ql[0], ql[1], ql[2], ql[3], sb + OQL + offQ);
#pragma unroll
            for (int n2 = 0; n2 < 4; n2++) {
                uint32_t bh[4], bl[4];
                uint32_t offK = (uint32_t)((n2 * 16 + laneRow) * FST + ks * 16 + laneK8) * 2;
                LDSM_X4(bh[0], bh[1], bh[2], bh[3], sb + OKH + offK);
                LDSM_X4(bl[0], bl[1], bl[2], bl[3], sb + OKL + offK);
                MMA16816(accS[2 * n2],     qh[ks], bh[0], bh[2]);
                MMA16816(accS[2 * n2 + 1], qh[ks], bh[1], bh[3]);
                MMA16816(accS[2 * n2],     qh[ks], bl[0], bl[2]);
                MMA16816(accS[2 * n2 + 1], qh[ks], bl[1], bl[3]);
                MMA16816(accS[2 * n2],     ql,     bh[0], bh[2]);
                MMA16816(accS[2 * n2 + 1], ql,     bh[1], bh[3]);
            }
        }

        // ---- mask + online softmax update (two row-halves) ----
        const int c0 = kc * 64;
#pragma unroll
        for (int h = 0; h < 2; h++) {
            const int gi = r0 + wid * 16 + qrow + 8 * h;
            float& m = (h == 0) ? m0 : m1;
            float& l = (h == 0) ? l0 : l1;
            float mx = -1e30f;
#pragma unroll
            for (int n = 0; n < 8; n++) {
                int col = c0 + n * 8 + qcol;
                if (col > gi)     accS[n][2 * h]     = -1e30f;
                if (col + 1 > gi) accS[n][2 * h + 1] = -1e30f;
                mx = fmaxf(mx, fmaxf(accS[n][2 * h], accS[n][2 * h + 1]));
            }
            mx = fmaxf(mx, __shfl_xor_sync(0xffffffffu, mx, 1));
            mx = fmaxf(mx, __shfl_xor_sync(0xffffffffu, mx, 2));
            float mn = fmaxf(m, mx);
            float sc = __expf(m - mn);
            float sum = 0.0f;
#pragma unroll
            for (int n = 0; n < 8; n++) {
                float p0 = __expf(accS[n][2 * h]     - mn);
                float p1 = __expf(accS[n][2 * h + 1] - mn);
                accS[n][2 * h] = p0;
                accS[n][2 * h + 1] = p1;
                sum += p0 + p1;
            }
            sum += __shfl_xor_sync(0xffffffffu, sum, 1);
            sum += __shfl_xor_sync(0xffffffffu, sum, 2);
            l = l * sc + sum;
            m = mn;
#pragma unroll
            for (int n = 0; n < 8; n++) {
                accO[n][2 * h]     *= sc;
                accO[n][2 * h + 1] *= sc;
            }
        }

        // ---- O += P V  (P in registers: C-frag -> A-frag identity) ----
#pragma unroll
        for (int t = 0; t < 4; t++) {
            uint32_t aph[4], apl[4];
            split2(accS[2 * t][0],     accS[2 * t][1],     aph[0], apl[0]);
            split2(accS[2 * t][2],     accS[2 * t][3],     aph[1], apl[1]);
            split2(accS[2 * t + 1][0], accS[2 * t + 1][1], aph[2], apl[2]);
            split2(accS[2 * t + 1][2], accS[2 * t + 1][3], aph[3], apl[3]);
            int kRow = t * 16 + (lane & 7) + ((lane >> 4) << 3);
#pragma unroll
            for (int n2 = 0; n2 < 4; n2++) {
                int nCol = n2 * 16 + ((lane >> 3) & 1) * 8;
                uint32_t offV = (uint32_t)(kRow * FST + nCol) * 2;
                uint32_t vh[4], vl[4];
                LDSM_X4_T(vh[0], vh[1], vh[2], vh[3], sb + OVH + offV);
                LDSM_X4_T(vl[0], vl[1], vl[2], vl[3], sb + OVL + offV);
                MMA16816(accO[2 * n2],     aph, vh[0], vh[2]);
                MMA16816(accO[2 * n2 + 1], aph, vh[1], vh[3]);
                MMA16816(accO[2 * n2],     aph, vl[0], vl[2]);
                MMA16816(accO[2 * n2 + 1], aph, vl[1], vl[3]);
                MMA16816(accO[2 * n2],     apl, vh[0], vh[2]);
                MMA16816(accO[2 * n2 + 1], apl, vh[1], vh[3]);
            }
        }
    }

    // ---- epilogue ----
    const float inv0 = 1.0f / l0;
    const float inv1 = 1.0f / l1;
    const int row = r0 + wid * 16 + qrow;
    const size_t base0 = (brow + row) * (size_t)HEAD;
    const size_t base1 = (brow + row + 8) * (size_t)HEAD;
#pragma unroll
    for (int n = 0; n < 8; n++) {
        *(float2*)&out[base0 + n * 8 + qcol] =
            make_float2(accO[n][0] * inv0, accO[n][1] * inv0);
        *(float2*)&out[base1 + n * 8 + qcol] =
            make_float2(accO[n][2] * inv1, accO[n][3] * inv1);
    }
}

// ---------------------------------------------------------------------------
extern "C" void kernel_launch(void* const* d_in, const int* in_sizes, int n_in,
                              void* d_out, int out_size)
{
    const float* x  = (const float*)d_in[0];
    const float* Wq = (const float*)d_in[1];
    const float* Wk = (const float*)d_in[2];
    const float* Wv = (const float*)d_in[3];
    float* out = (float*)d_out;

    (void)in_sizes; (void)n_in; (void)out_size;

    cudaFuncSetAttribute(qkv_mma_kernel,
                         cudaFuncAttributeMaxDynamicSharedMemorySize,
                         QKV_SMEM_BYTES);
    cudaFuncSetAttribute(flash_kernel,
                         cudaFuncAttributeMaxDynamicSharedMemorySize,
                         FLASH_SMEM_BYTES);

    wprep_kernel<<<(NQKV * CEMB + 255) / 256, 256>>>(Wq, Wk, Wv);
    qkv_mma_kernel<<<MROWS / 128, 256, QKV_SMEM_BYTES>>>(x);
    flash_kernel<<<dim3(2, BATCH), 256, FLASH_SMEM_BYTES>>>(out);
}

// round 12
// speedup vs baseline: 5.9923x; 1.1854x over previous
#include <cuda_runtime.h>
#include <cuda_bf16.h>
#include <cstdint>

// Problem constants
#define BATCH 512
#define SEQ   256
#define CEMB  384
#define HEAD  64
#define MROWS (BATCH * SEQ)          // 131072
#define NQKV  (3 * HEAD)             // 192
#define SCALE 0.05103103630798288f   // 384^-0.5

// Scratch buffers
__device__ __nv_bfloat16 g_WThi[NQKV * CEMB];
__device__ __nv_bfloat16 g_WTlo[NQKV * CEMB];
__device__ __nv_bfloat16 g_Qhi[(size_t)MROWS * HEAD];   // Q pre-scaled
__device__ __nv_bfloat16 g_Qlo[(size_t)MROWS * HEAD];
__device__ __nv_bfloat16 g_Khi[(size_t)MROWS * HEAD];
__device__ __nv_bfloat16 g_Klo[(size_t)MROWS * HEAD];
__device__ __nv_bfloat16 g_Vhi[(size_t)MROWS * HEAD];
__device__ __nv_bfloat16 g_Vlo[(size_t)MROWS * HEAD];

// ---------------------------------------------------------------------------
// Warp-MMA / async-copy helpers (baseline PTX, legal on .target sm_103)
// ---------------------------------------------------------------------------
__device__ __forceinline__ uint32_t smem_to_u32(const void* p) {
    uint32_t a;
    asm("{ .reg .u64 t; cvta.to.shared.u64 t, %1; cvt.u32.u64 %0, t; }"
        : "=r"(a) : "l"(p));
    return a;
}

#define LDSM_X4(r0, r1, r2, r3, addr) \
    asm volatile("ldmatrix.sync.aligned.m8n8.x4.shared.b16 {%0,%1,%2,%3}, [%4];" \
        : "=r"(r0), "=r"(r1), "=r"(r2), "=r"(r3) : "r"(addr))

#define LDSM_X4_T(r0, r1, r2, r3, addr) \
    asm volatile("ldmatrix.sync.aligned.m8n8.x4.trans.shared.b16 {%0,%1,%2,%3}, [%4];" \
        : "=r"(r0), "=r"(r1), "=r"(r2), "=r"(r3) : "r"(addr))

#define MMA16816(d, a, b0, b1) \
    asm volatile("mma.sync.aligned.m16n8k16.row.col.f32.bf16.bf16.f32 " \
        "{%0,%1,%2,%3}, {%4,%5,%6,%7}, {%8,%9}, {%0,%1,%2,%3};" \
        : "+f"((d)[0]), "+f"((d)[1]), "+f"((d)[2]), "+f"((d)[3]) \
        : "r"((a)[0]), "r"((a)[1]), "r"((a)[2]), "r"((a)[3]), \
          "r"(b0), "r"(b1))

#define CP_ASYNC16(dst_u32, src_ptr) \
    asm volatile("cp.async.cg.shared.global [%0], [%1], 16;" \
        :: "r"(dst_u32), "l"(src_ptr))
#define CP_COMMIT() asm volatile("cp.async.commit_group;")
#define CP_WAIT0()  asm volatile("cp.async.wait_group 0;" ::: "memory")

// fp32 pair -> bf16 hi/lo packed pairs
__device__ __forceinline__ void split2(float a, float b, uint32_t& hi, uint32_t& lo) {
    __nv_bfloat16 ha = __float2bfloat16(a);
    __nv_bfloat16 hb = __float2bfloat16(b);
    __nv_bfloat16 la = __float2bfloat16(a - __bfloat162float(ha));
    __nv_bfloat16 lb = __float2bfloat16(b - __bfloat162float(hb));
    __nv_bfloat162 hp = __halves2bfloat162(ha, hb);
    __nv_bfloat162 lp = __halves2bfloat162(la, lb);
    hi = *(uint32_t*)&hp;
    lo = *(uint32_t*)&lp;
}

// ---------------------------------------------------------------------------
// Prep: W^T + bf16 hi/lo split.  g_WT[n][k] = W[k][n], n = mat*64 + h
// ---------------------------------------------------------------------------
__global__ void wprep_kernel(const float* __restrict__ Wq,
                             const float* __restrict__ Wk,
                             const float* __restrict__ Wv)
{
    int idx = blockIdx.x * 256 + threadIdx.x;
    if (idx >= NQKV * CEMB) return;
    int n = idx / CEMB, k = idx % CEMB;
    int mat = n >> 6, h = n & 63;
    const float* W = (mat == 0) ? Wq : (mat == 1) ? Wk : Wv;
    float v = W[k * HEAD + h];
    __nv_bfloat16 hi = __float2bfloat16(v);
    g_WThi[idx] = hi;
    g_WTlo[idx] = __float2bfloat16(v - __bfloat162float(hi));
}

// ---------------------------------------------------------------------------
// QKV projection via HMMA, bf16 split-accumulate, pipelined.
// BM=64, BN=192, BK=32; 256 threads; warps 2(M) x 4(N), warp tile 32x48.
// Double-buffered smem: W tiles via cp.async, x tile via register prefetch.
// ---------------------------------------------------------------------------
#define QPAD 40
#define A_EL (64 * QPAD)             // 2560 elems per A buffer (hi or lo)
#define B_EL (192 * QPAD)            // 7680 elems per B buffer
#define BUF_EL (2 * A_EL + 2 * B_EL) // 20480 per stage
#define OAH(p) ((p) * BUF_EL)
#define OAL(p) (OAH(p) + A_EL)
#define OBH(p) (OAH(p) + 2 * A_EL)
#define OBL(p) (OBH(p) + B_EL)
#define QKV_SMEM_BYTES (2 * BUF_EL * 2)   // 81920

__global__ __launch_bounds__(256, 2) void qkv_mma_kernel(const float* __restrict__ x)
{
    extern __shared__ __nv_bfloat16 smq[];
    const uint32_t sbase = smem_to_u32(smq);
    const int tid   = threadIdx.x;
    const int lane  = tid & 31;
    const int wid   = tid >> 5;
    const int warpM = wid & 1;        // rows warpM*32
    const int warpN = wid >> 1;       // cols warpN*48
    const int row0  = blockIdx.x * 64;

    const int laneRow = lane & 15;
    const int laneK   = (lane >> 4) << 3;

    // x prefetch mapping: thread -> (row, 8-float group)
    const int ar = tid >> 2;          // 0..63
    const int ag = tid & 3;           // 0..3  (8 floats each)

    // W tile mapping for 16B cp.async groups: 192 rows x 4 groups = 768
    // per buffer; 3 iterations of 256 threads; r = li>>2, g = li&3.
    float acc[2][6][4];
#pragma unroll
    for (int mt = 0; mt < 2; mt++)
#pragma unroll
        for (int nt = 0; nt < 6; nt++)
#pragma unroll
            for (int e = 0; e < 4; e++) acc[mt][nt][e] = 0.0f;

    // ---- prologue: stage chunk 0 into buffer 0 ----
    {
        const float4* s = (const float4*)&x[(size_t)(row0 + ar) * CEMB + ag * 8];
        float4 a0 = s[0], a1 = s[1];
        uint4 hw, lw;
        split2(a0.x, a0.y, hw.x, lw.x);
        split2(a0.z, a0.w, hw.y, lw.y);
        split2(a1.x, a1.y, hw.z, lw.z);
        split2(a1.z, a1.w, hw.w, lw.w);
        *(uint4*)&smq[OAH(0) + ar * QPAD + ag * 8] = hw;
        *(uint4*)&smq[OAL(0) + ar * QPAD + ag * 8] = lw;
#pragma unroll
        for (int i = 0; i < 3; i++) {
            int li = tid + i * 256;           // 768 x 16B groups per buffer
            int r = li >> 2, g = li & 3;
            CP_ASYNC16(sbase + (OBH(0) + r * QPAD + g * 8) * 2,
                       (const void*)&g_WThi[(size_t)r * CEMB + g * 8]);
            CP_ASYNC16(sbase + (OBL(0) + r * QPAD + g * 8) * 2,
                       (const void*)&g_WTlo[(size_t)r * CEMB + g * 8]);
        }
        CP_COMMIT();
        CP_WAIT0();
        __syncthreads();
    }

    for (int c = 0; c < 12; c++) {
        const int p = c & 1;
        const bool pre = (c < 11);
        float4 pa0, pa1;
        if (pre) {
            const int k1 = (c + 1) * 32;
            const float4* s = (const float4*)&x[(size_t)(row0 + ar) * CEMB + k1 + ag * 8];
            pa0 = s[0]; pa1 = s[1];
#pragma unroll
            for (int i = 0; i < 3; i++) {
                int li = tid + i * 256;
                int r = li >> 2, g = li & 3;
                CP_ASYNC16(sbase + (OBH(p ^ 1) + r * QPAD + g * 8) * 2,
                           (const void*)&g_WThi[(size_t)r * CEMB + k1 + g * 8]);
                CP_ASYNC16(sbase + (OBL(p ^ 1) + r * QPAD + g * 8) * 2,
                           (const void*)&g_WTlo[(size_t)r * CEMB + k1 + g * 8]);
            }
            CP_COMMIT();
        }

        // ---- compute chunk c from buffer p ----
#pragma unroll
        for (int ks = 0; ks < 2; ks++) {
            const int kk = ks * 16 + laneK;
            uint32_t ahi[2][4], alo[2][4];
#pragma unroll
            for (int mt = 0; mt < 2; mt++) {
                uint32_t off = (uint32_t)((warpM * 32 + mt * 16 + laneRow) * QPAD + kk) * 2;
                LDSM_X4(ahi[mt][0], ahi[mt][1], ahi[mt][2], ahi[mt][3],
                        sbase + OAH(p) * 2 + off);
                LDSM_X4(alo[mt][0], alo[mt][1], alo[mt][2], alo[mt][3],
                        sbase + OAL(p) * 2 + off);
            }
#pragma unroll
            for (int pp = 0; pp < 3; pp++) {
                const uint32_t bBase = (pp == 1) ? (uint32_t)(OBL(p) * 2)
                                                 : (uint32_t)(OBH(p) * 2);
                uint32_t (*A)[4] = (pp < 2) ? ahi : alo;
                uint32_t bf[3][4];
#pragma unroll
                for (int j = 0; j < 3; j++) {
                    uint32_t off = (uint32_t)((warpN * 48 + j * 16 + laneRow) * QPAD + kk) * 2;
                    LDSM_X4(bf[j][0], bf[j][1], bf[j][2], bf[j][3], sbase + bBase + off);
                }
#pragma unroll
                for (int mt = 0; mt < 2; mt++)
#pragma unroll
                    for (int j = 0; j < 3; j++) {
                        MMA16816(acc[mt][2 * j],     A[mt], bf[j][0], bf[j][2]);
                        MMA16816(acc[mt][2 * j + 1], A[mt], bf[j][1], bf[j][3]);
                    }
            }
        }

        if (pre) {
            uint4 hw, lw;
            split2(pa0.x, pa0.y, hw.x, lw.x);
            split2(pa0.z, pa0.w, hw.y, lw.y);
            split2(pa1.x, pa1.y, hw.z, lw.z);
            split2(pa1.z, pa1.w, hw.w, lw.w);
            *(uint4*)&smq[OAH(p ^ 1) + ar * QPAD + ag * 8] = hw;
            *(uint4*)&smq[OAL(p ^ 1) + ar * QPAD + ag * 8] = lw;
            CP_WAIT0();
        }
        __syncthreads();
    }

    // ---- epilogue: split to bf16 hi/lo, route to Q (scaled) / K / V ----
    const int qrow = lane >> 2;
    const int qcol = (lane & 3) * 2;
#pragma unroll
    for (int mt = 0; mt < 2; mt++) {
#pragma unroll
        for (int h = 0; h < 2; h++) {
            int row = row0 + warpM * 32 + mt * 16 + qrow + 8 * h;
#pragma unroll
            for (int j = 0; j < 6; j++) {
                int n = warpN * 48 + j * 8 + qcol;
                int mat = n >> 6;
                int cc  = n & 63;
                float v0 = acc[mt][j][2 * h];
                float v1 = acc[mt][j][2 * h + 1];
                if (mat == 0) { v0 *= SCALE; v1 *= SCALE; }
                uint32_t hp, lp;
                split2(v0, v1, hp, lp);
                __nv_bfloat16* bhi = (mat == 0) ? g_Qhi : (mat == 1) ? g_Khi : g_Vhi;
                __nv_bfloat16* blo = (mat == 0) ? g_Qlo : (mat == 1) ? g_Klo : g_Vlo;
                size_t o = (size_t)row * HEAD + cc;
                *(uint32_t*)&bhi[o] = hp;
                *(uint32_t*)&blo[o] = lp;
            }
        }
    }
}

// ---------------------------------------------------------------------------
// Flash-attention-2 style attention (unchanged from R6, known good).
// ---------------------------------------------------------------------------
#define FST 72
#define OQH 0
#define OQL (128 * FST * 2)
#define OKH (2 * 128 * FST * 2)
#define OKL (OKH + 64 * FST * 2)
#define OVH (OKL + 64 * FST * 2)
#define OVL (OVH + 64 * FST * 2)
#define FLASH_SMEM_BYTES (OVL + 64 * FST * 2)   // 73728

__global__ __launch_bounds__(256, 2) void flash_kernel(float* __restrict__ out)
{
    extern __shared__ char sm[];
    __nv_bfloat16* sbf = (__nv_bfloat16*)sm;
    const uint32_t sb = smem_to_u32(sm);
    const int tid = threadIdx.x, lane = tid & 31, wid = tid >> 5;
    const int rt = blockIdx.x, batch = blockIdx.y;
    const int r0 = rt * 128;
    const size_t brow = (size_t)batch * SEQ;
    const int qrow = lane >> 2, qcol = (lane & 3) * 2;
    const int laneRow = lane & 15, laneK8 = (lane >> 4) << 3;

#pragma unroll
    for (int i = 0; i < 4; i++) {
        int li = tid + i * 256;
        int r = li >> 3, g = li & 7;
        size_t src = (brow + r0 + r) * HEAD + g * 8;
        *(uint4*)&sbf[OQH / 2 + r * FST + g * 8] = *(const uint4*)&g_Qhi[src];
        *(uint4*)&sbf[OQL / 2 + r * FST + g * 8] = *(const uint4*)&g_Qlo[src];
    }
    __syncthreads();

    uint32_t qh[4][4];
#pragma unroll
    for (int ks = 0; ks < 4; ks++) {
        uint32_t off = (uint32_t)((wid * 16 + laneRow) * FST + ks * 16 + laneK8) * 2;
        LDSM_X4(qh[ks][0], qh[ks][1], qh[ks][2], qh[ks][3], sb + OQH + off);
    }

    float accO[8][4];
#pragma unroll
    for (int n = 0; n < 8; n++)
#pragma unroll
        for (int e = 0; e < 4; e++) accO[n][e] = 0.0f;
    float m0 = -1e30f, m1 = -1e30f, l0 = 0.0f, l1 = 0.0f;

    const int nch = 2 * (rt + 1);
    for (int kc = 0; kc < nch; kc++) {
        __syncthreads();
#pragma unroll
        for (int i = 0; i < 2; i++) {
            int li = tid + i * 256;
            int r = li >> 3, g = li & 7;
            size_t src = (brow + kc * 64 + r) * HEAD + g * 8;
            *(uint4*)&sbf[OKH / 2 + r * FST + g * 8] = *(const uint4*)&g_Khi[src];
            *(uint4*)&sbf[OKL / 2 + r * FST + g * 8] = *(const uint4*)&g_Klo[src];
            *(uint4*)&sbf[OVH / 2 + r * FST + g * 8] = *(const uint4*)&g_Vhi[src];
            *(uint4*)&sbf[OVL / 2 + r * FST + g * 8] = *(const uint4*)&g_Vlo[src];
        }
        __syncthreads();

        float accS[8][4];
#pragma unroll
        for (int n = 0; n < 8; n++)
#pragma unroll
            for (int e = 0; e < 4; e++) accS[n][e] = 0.0f;

#pragma unroll
        for (int ks = 0; ks < 4; ks++) {
            uint32_t ql[4];
            uint32_t offQ = (uint32_t)((wid * 16 + laneRow) * FST + ks * 16 + laneK8) * 2;
            LDSM_X4(ql[0], ql[1], ql[2], ql[3], sb + OQL + offQ);
#pragma unroll
            for (int n2 = 0; n2 < 4; n2++) {
                uint32_t bh[4], bl[4];
                uint32_t offK = (uint32_t)((n2 * 16 + laneRow) * FST + ks * 16 + laneK8) * 2;
                LDSM_X4(bh[0], bh[1], bh[2], bh[3], sb + OKH + offK);
                LDSM_X4(bl[0], bl[1], bl[2], bl[3], sb + OKL + offK);
                MMA16816(accS[2 * n2],     qh[ks], bh[0], bh[2]);
                MMA16816(accS[2 * n2 + 1], qh[ks], bh[1], bh[3]);
                MMA16816(accS[2 * n2],     qh[ks], bl[0], bl[2]);
                MMA16816(accS[2 * n2 + 1], qh[ks], bl[1], bl[3]);
                MMA16816(accS[2 * n2],     ql,     bh[0], bh[2]);
                MMA16816(accS[2 * n2 + 1], ql,     bh[1], bh[3]);
            }
        }

        const int c0 = kc * 64;
#pragma unroll
        for (int h = 0; h < 2; h++) {
            const int gi = r0 + wid * 16 + qrow + 8 * h;
            float& m = (h == 0) ? m0 : m1;
            float& l = (h == 0) ? l0 : l1;
            float mx = -1e30f;
#pragma unroll
            for (int n = 0; n < 8; n++) {
                int col = c0 + n * 8 + qcol;
                if (col > gi)     accS[n][2 * h]     = -1e30f;
                if (col + 1 > gi) accS[n][2 * h + 1] = -1e30f;
                mx = fmaxf(mx, fmaxf(accS[n][2 * h], accS[n][2 * h + 1]));
            }
            mx = fmaxf(mx, __shfl_xor_sync(0xffffffffu, mx, 1));
            mx = fmaxf(mx, __shfl_xor_sync(0xffffffffu, mx, 2));
            float mn = fmaxf(m, mx);
            float sc = __expf(m - mn);
            float sum = 0.0f;
#pragma unroll
            for (int n = 0; n < 8; n++) {
                float p0 = __expf(accS[n][2 * h]     - mn);
                float p1 = __expf(accS[n][2 * h + 1] - mn);
                accS[n][2 * h] = p0;
                accS[n][2 * h + 1] = p1;
                sum += p0 + p1;
            }
            sum += __shfl_xor_sync(0xffffffffu, sum, 1);
            sum += __shfl_xor_sync(0xffffffffu, sum, 2);
            l = l * sc + sum;
            m = mn;
#pragma unroll
            for (int n = 0; n < 8; n++) {
                accO[n][2 * h]     *= sc;
                accO[n][2 * h + 1] *= sc;
            }
        }

#pragma unroll
        for (int t = 0; t < 4; t++) {
            uint32_t aph[4], apl[4];
            split2(accS[2 * t][0],     accS[2 * t][1],     aph[0], apl[0]);
            split2(accS[2 * t][2],     accS[2 * t][3],     aph[1], apl[1]);
            split2(accS[2 * t + 1][0], accS[2 * t + 1][1], aph[2], apl[2]);
            split2(accS[2 * t + 1][2], accS[2 * t + 1][3], aph[3], apl[3]);
            int kRow = t * 16 + (lane & 7) + ((lane >> 4) << 3);
#pragma unroll
            for (int n2 = 0; n2 < 4; n2++) {
                int nCol = n2 * 16 + ((lane >> 3) & 1) * 8;
                uint32_t offV = (uint32_t)(kRow * FST + nCol) * 2;
                uint32_t vh[4], vl[4];
                LDSM_X4_T(vh[0], vh[1], vh[2], vh[3], sb + OVH + offV);
                LDSM_X4_T(vl[0], vl[1], vl[2], vl[3], sb + OVL + offV);
                MMA16816(accO[2 * n2],     aph, vh[0], vh[2]);
                MMA16816(accO[2 * n2 + 1], aph, vh[1], vh[3]);
                MMA16816(accO[2 * n2],     aph, vl[0], vl[2]);
                MMA16816(accO[2 * n2 + 1], aph, vl[1], vl[3]);
                MMA16816(accO[2 * n2],     apl, vh[0], vh[2]);
                MMA16816(accO[2 * n2 + 1], apl, vh[1], vh[3]);
            }
        }
    }

    const float inv0 = 1.0f / l0;
    const float inv1 = 1.0f / l1;
    const int row = r0 + wid * 16 + qrow;
    const size_t base0 = (brow + row) * (size_t)HEAD;
    const size_t base1 = (brow + row + 8) * (size_t)HEAD;
#pragma unroll
    for (int n = 0; n < 8; n++) {
        *(float2*)&out[base0 + n * 8 + qcol] =
            make_float2(accO[n][0] * inv0, accO[n][1] * inv0);
        *(float2*)&out[base1 + n * 8 + qcol] =
            make_float2(accO[n][2] * inv1, accO[n][3] * inv1);
    }
}

// ---------------------------------------------------------------------------
extern "C" void kernel_launch(void* const* d_in, const int* in_sizes, int n_in,
                              void* d_out, int out_size)
{
    const float* x  = (const float*)d_in[0];
    const float* Wq = (const float*)d_in[1];
    const float* Wk = (const float*)d_in[2];
    const float* Wv = (const float*)d_in[3];
    float* out = (float*)d_out;

    (void)in_sizes; (void)n_in; (void)out_size;

    cudaFuncSetAttribute(qkv_mma_kernel,
                         cudaFuncAttributeMaxDynamicSharedMemorySize,
                         QKV_SMEM_BYTES);
    cudaFuncSetAttribute(flash_kernel,
                         cudaFuncAttributeMaxDynamicSharedMemorySize,
                         FLASH_SMEM_BYTES);

    wprep_kernel<<<(NQKV * CEMB + 255) / 256, 256>>>(Wq, Wk, Wv);
    qkv_mma_kernel<<<MROWS / 64, 256, QKV_SMEM_BYTES>>>(x);
    flash_kernel<<<dim3(2, BATCH), 256, FLASH_SMEM_BYTES>>>(out);
}

// round 15
// speedup vs baseline: 7.8775x; 1.3146x over previous
#include <cuda_runtime.h>
#include <cuda_bf16.h>
#include <cstdint>

// Problem constants
#define BATCH 512
#define SEQ   256
#define CEMB  384
#define HEAD  64
#define MROWS (BATCH * SEQ)          // 131072
#define NQKV  (3 * HEAD)             // 192
#define SCALE 0.05103103630798288f   // 384^-0.5

// Scratch buffers (all values stored pre-rounded to tf32)
__device__ float g_WT[NQKV * CEMB];               // W^T [n][k]
__device__ float g_Q[(size_t)MROWS * HEAD];       // Q pre-scaled
__device__ float g_K[(size_t)MROWS * HEAD];
__device__ float g_V[(size_t)MROWS * HEAD];

// ---------------------------------------------------------------------------
// Helpers (baseline PTX, legal on .target sm_103)
// ---------------------------------------------------------------------------
__device__ __forceinline__ uint32_t smem_to_u32(const void* p) {
    uint32_t a;
    asm("{ .reg .u64 t; cvta.to.shared.u64 t, %1; cvt.u32.u64 %0, t; }"
        : "=r"(a) : "l"(p));
    return a;
}

__device__ __forceinline__ uint32_t f2tf(float f) {
    uint32_t u;
    asm("cvt.rna.tf32.f32 %0, %1;" : "=r"(u) : "f"(f));
    return u;
}

// D += A(m16k8, tf32) * B(k8n8, tf32)
#define MMATF(d, a, b0, b1) \
    asm volatile("mma.sync.aligned.m16n8k8.row.col.f32.tf32.tf32.f32 " \
        "{%0,%1,%2,%3}, {%4,%5,%6,%7}, {%8,%9}, {%0,%1,%2,%3};" \
        : "+f"((d)[0]), "+f"((d)[1]), "+f"((d)[2]), "+f"((d)[3]) \
        : "r"((a)[0]), "r"((a)[1]), "r"((a)[2]), "r"((a)[3]), \
          "r"(b0), "r"(b1))

#define CP_ASYNC16(dst_u32, src_ptr) \
    asm volatile("cp.async.cg.shared.global [%0], [%1], 16;" \
        :: "r"(dst_u32), "l"(src_ptr))
#define CP_COMMIT() asm volatile("cp.async.commit_group;")
#define CP_WAIT0()  asm volatile("cp.async.wait_group 0;" ::: "memory")

// ---------------------------------------------------------------------------
// Prep: W^T, rounded to tf32.  g_WT[n][k] = tf32(W[k][n]), n = mat*64 + h
// ---------------------------------------------------------------------------
__global__ void wprep_kernel(const float* __restrict__ Wq,
                             const float* __restrict__ Wk,
                             const float* __restrict__ Wv)
{
    int idx = blockIdx.x * 256 + threadIdx.x;
    if (idx >= NQKV * CEMB) return;
    int n = idx / CEMB, k = idx % CEMB;
    int mat = n >> 6, h = n & 63;
    const float* W = (mat == 0) ? Wq : (mat == 1) ? Wk : Wv;
    g_WT[idx] = __uint_as_float(f2tf(W[k * HEAD + h]));
}

// ---------------------------------------------------------------------------
// QKV projection, single-pass tf32 HMMA, double-buffered pipeline.
// BM=64, BN=192, BK=32; 256 threads; warps 2(M) x 4(N), warp tile 32x48.
// Fragments gathered with scalar LDS (pad-36 rows: bank=(4g+t)%32, distinct).
// ---------------------------------------------------------------------------
#define QPW 36                        // fp32 words per smem row (144B, 16B-aligned)
#define A_F (64 * QPW)                // 2304 floats
#define B_F (192 * QPW)               // 6912 floats
#define STG (A_F + B_F)               // 9216 floats per stage
#define OA(p) ((p) * STG)
#define OB(p) (OA(p) + A_F)
#define QKV_SMEM_BYTES (2 * STG * 4)  // 73728

__global__ __launch_bounds__(256, 2) void qkv_mma_kernel(const float* __restrict__ x)
{
    extern __shared__ float smq[];
    const uint32_t sbase = smem_to_u32(smq);
    const int tid   = threadIdx.x;
    const int lane  = tid & 31;
    const int wid   = tid >> 5;
    const int warpM = wid & 1;        // rows warpM*32
    const int warpN = wid >> 1;       // cols warpN*48
    const int row0  = blockIdx.x * 64;

    const int g4 = lane >> 2;         // 0..7
    const int t4 = lane & 3;          // 0..3

    // x staging mapping: thread -> (row, 8-float group)
    const int ar = tid >> 2;          // 0..63
    const int ag = tid & 3;           // 0..3

    float acc[2][6][4];
#pragma unroll
    for (int mt = 0; mt < 2; mt++)
#pragma unroll
        for (int nt = 0; nt < 6; nt++)
#pragma unroll
            for (int e = 0; e < 4; e++) acc[mt][nt][e] = 0.0f;

    // ---- prologue: stage chunk 0 into buffer 0 ----
    {
        const float4* s = (const float4*)&x[(size_t)(row0 + ar) * CEMB + ag * 8];
        float4 a0 = s[0], a1 = s[1];
        uint4 w0 = make_uint4(f2tf(a0.x), f2tf(a0.y), f2tf(a0.z), f2tf(a0.w));
        uint4 w1 = make_uint4(f2tf(a1.x), f2tf(a1.y), f2tf(a1.z), f2tf(a1.w));
        *(uint4*)&smq[OA(0) + ar * QPW + ag * 8]     = w0;
        *(uint4*)&smq[OA(0) + ar * QPW + ag * 8 + 4] = w1;
#pragma unroll
        for (int i = 0; i < 6; i++) {
            int li = tid + i * 256;           // 1536 x 16B groups
            int r = li >> 3, g = li & 7;
            CP_ASYNC16(sbase + (OB(0) + r * QPW + g * 4) * 4,
                       (const void*)&g_WT[(size_t)r * CEMB + g * 4]);
        }
        CP_COMMIT();
        CP_WAIT0();
        __syncthreads();
    }

    for (int c = 0; c < 12; c++) {
        const int p = c & 1;
        const bool pre = (c < 11);
        float4 pa0, pa1;
        if (pre) {
            const int k1 = (c + 1) * 32;
            const float4* s = (const float4*)&x[(size_t)(row0 + ar) * CEMB + k1 + ag * 8];
            pa0 = s[0]; pa1 = s[1];
#pragma unroll
            for (int i = 0; i < 6; i++) {
                int li = tid + i * 256;
                int r = li >> 3, g = li & 7;
                CP_ASYNC16(sbase + (OB(p ^ 1) + r * QPW + g * 4) * 4,
                           (const void*)&g_WT[(size_t)r * CEMB + k1 + g * 4]);
            }
            CP_COMMIT();
        }

        // ---- compute chunk c from buffer p ----
#pragma unroll
        for (int ks = 0; ks < 4; ks++) {
            const int kk = ks * 8;
            uint32_t af[2][4];
#pragma unroll
            for (int mt = 0; mt < 2; mt++) {
                const int m = warpM * 32 + mt * 16;
                const float* A = &smq[OA(p) + kk + t4];
                af[mt][0] = *(const uint32_t*)&A[(m + g4) * QPW];
                af[mt][1] = *(const uint32_t*)&A[(m + g4 + 8) * QPW];
                af[mt][2] = *(const uint32_t*)&A[(m + g4) * QPW + 4];
                af[mt][3] = *(const uint32_t*)&A[(m + g4 + 8) * QPW + 4];
            }
            uint32_t bf[6][2];
#pragma unroll
            for (int j = 0; j < 6; j++) {
                const int n = warpN * 48 + j * 8;
                const float* B = &smq[OB(p) + (n + g4) * QPW + kk + t4];
                bf[j][0] = *(const uint32_t*)&B[0];
                bf[j][1] = *(const uint32_t*)&B[4];
            }
#pragma unroll
            for (int mt = 0; mt < 2; mt++)
#pragma unroll
                for (int j = 0; j < 6; j++)
                    MMATF(acc[mt][j], af[mt], bf[j][0], bf[j][1]);
        }

        if (pre) {
            uint4 w0 = make_uint4(f2tf(pa0.x), f2tf(pa0.y), f2tf(pa0.z), f2tf(pa0.w));
            uint4 w1 = make_uint4(f2tf(pa1.x), f2tf(pa1.y), f2tf(pa1.z), f2tf(pa1.w));
            *(uint4*)&smq[OA(p ^ 1) + ar * QPW + ag * 8]     = w0;
            *(uint4*)&smq[OA(p ^ 1) + ar * QPW + ag * 8 + 4] = w1;
            CP_WAIT0();
        }
        __syncthreads();
    }

    // ---- epilogue: round to tf32, route to Q (scaled) / K / V ----
#pragma unroll
    for (int mt = 0; mt < 2; mt++) {
#pragma unroll
        for (int h = 0; h < 2; h++) {
            int row = row0 + warpM * 32 + mt * 16 + g4 + 8 * h;
#pragma unroll
            for (int j = 0; j < 6; j++) {
                int n = warpN * 48 + j * 8 + t4 * 2;
                int mat = n >> 6;
                int cc  = n & 63;
                float v0 = acc[mt][j][2 * h];
                float v1 = acc[mt][j][2 * h + 1];
                if (mat == 0) { v0 *= SCALE; v1 *= SCALE; }
                float* dst = (mat == 0) ? g_Q : (mat == 1) ? g_K : g_V;
                *(float2*)&dst[(size_t)row * HEAD + cc] =
                    make_float2(__uint_as_float(f2tf(v0)), __uint_as_float(f2tf(v1)));
            }
        }
    }
}

// ---------------------------------------------------------------------------
// Flash-attention-2, single-pass tf32.
// Block = (128-row tile, batch). 8 warps x 16 rows. Online softmax.
// P C-frag -> A-frag via quad shuffles (cols 2t,2t+1 -> t, t+4).
// ---------------------------------------------------------------------------
#define FPW 68
#define FOQ 0
#define FOK (128 * FPW)               // 8704
#define FOV (FOK + 64 * FPW)          // 13056
#define FLASH_SMEM_BYTES ((FOV + 64 * FPW) * 4)   // 69632

__global__ __launch_bounds__(256, 2) void flash_kernel(float* __restrict__ out)
{
    extern __shared__ float smf[];
    const int tid = threadIdx.x, lane = tid & 31, wid = tid >> 5;
    const int rt = blockIdx.x, batch = blockIdx.y;
    const int r0 = rt * 128;
    const size_t brow = (size_t)batch * SEQ;
    const int g4 = lane >> 2;         // qrow
    const int t4 = lane & 3;
    const int qcol = t4 * 2;

    // Load Q tile (128 rows x 64, fp32/tf32)
#pragma unroll
    for (int i = 0; i < 8; i++) {
        int li = tid + i * 256;
        int r = li >> 4, g = li & 15;
        *(uint4*)&smf[FOQ + r * FPW + g * 4] =
            *(const uint4*)&g_Q[(brow + r0 + r) * HEAD + g * 4];
    }
    __syncthreads();

    float accO[8][4];
#pragma unroll
    for (int n = 0; n < 8; n++)
#pragma unroll
        for (int e = 0; e < 4; e++) accO[n][e] = 0.0f;
    float m0 = -1e30f, m1 = -1e30f, l0 = 0.0f, l1 = 0.0f;

    const int nch = 2 * (rt + 1);
    for (int kc = 0; kc < nch; kc++) {
        __syncthreads();
#pragma unroll
        for (int i = 0; i < 4; i++) {
            int li = tid + i * 256;
            int r = li >> 4, g = li & 15;
            size_t src = (brow + kc * 64 + r) * HEAD + g * 4;
            *(uint4*)&smf[FOK + r * FPW + g * 4] = *(const uint4*)&g_K[src];
            *(uint4*)&smf[FOV + r * FPW + g * 4] = *(const uint4*)&g_V[src];
        }
        __syncthreads();

        // ---- S = Q K^T ----
        float accS[8][4];
#pragma unroll
        for (int n = 0; n < 8; n++)
#pragma unroll
            for (int e = 0; e < 4; e++) accS[n][e] = 0.0f;

        const int mrow = wid * 16;
#pragma unroll
        for (int ks = 0; ks < 8; ks++) {
            const int kk = ks * 8;
            uint32_t af[4];
            {
                const float* A = &smf[FOQ + kk + t4];
                af[0] = *(const uint32_t*)&A[(mrow + g4) * FPW];
                af[1] = *(const uint32_t*)&A[(mrow + g4 + 8) * FPW];
                af[2] = *(const uint32_t*)&A[(mrow + g4) * FPW + 4];
                af[3] = *(const uint32_t*)&A[(mrow + g4 + 8) * FPW + 4];
            }
#pragma unroll
            for (int n2 = 0; n2 < 8; n2++) {
                const float* B = &smf[FOK + (n2 * 8 + g4) * FPW + kk + t4];
                uint32_t b0 = *(const uint32_t*)&B[0];
                uint32_t b1 = *(const uint32_t*)&B[4];
                MMATF(accS[n2], af, b0, b1);
            }
        }

        // ---- mask + online softmax update ----
        const int c0 = kc * 64;
#pragma unroll
        for (int h = 0; h < 2; h++) {
            const int gi = r0 + wid * 16 + g4 + 8 * h;
            float& m = (h == 0) ? m0 : m1;
            float& l = (h == 0) ? l0 : l1;
            float mx = -1e30f;
#pragma unroll
            for (int n = 0; n < 8; n++) {
                int col = c0 + n * 8 + qcol;
                if (col > gi)     accS[n][2 * h]     = -1e30f;
                if (col + 1 > gi) accS[n][2 * h + 1] = -1e30f;
                mx = fmaxf(mx, fmaxf(accS[n][2 * h], accS[n][2 * h + 1]));
            }
            mx = fmaxf(mx, __shfl_xor_sync(0xffffffffu, mx, 1));
            mx = fmaxf(mx, __shfl_xor_sync(0xffffffffu, mx, 2));
            float mn = fmaxf(m, mx);
            float sc = __expf(m - mn);
            float sum = 0.0f;
#pragma unroll
            for (int n = 0; n < 8; n++) {
                float p0 = __expf(accS[n][2 * h]     - mn);
                float p1 = __expf(accS[n][2 * h + 1] - mn);
                accS[n][2 * h] = p0;
                accS[n][2 * h + 1] = p1;
                sum += p0 + p1;
            }
            sum += __shfl_xor_sync(0xffffffffu, sum, 1);
            sum += __shfl_xor_sync(0xffffffffu, sum, 2);
            l = l * sc + sum;
            m = mn;
#pragma unroll
            for (int n = 0; n < 8; n++) {
                accO[n][2 * h]     *= sc;
                accO[n][2 * h + 1] *= sc;
            }
        }

        // ---- O += P V : C-frag -> A-frag quad shuffle, then MMA ----
        const int srcA = (lane & ~3) | (t4 >> 1);
        const int srcB = srcA + 2;
        const bool oddt = (t4 & 1);
#pragma unroll
        for (int j = 0; j < 8; j++) {
            float v00 = __shfl_sync(0xffffffffu, accS[j][0], srcA);
            float v01 = __shfl_sync(0xffffffffu, accS[j][1], srcA);
            float v02 = __shfl_sync(0xffffffffu, accS[j][2], srcA);
            float v03 = __shfl_sync(0xffffffffu, accS[j][3], srcA);
            float v10 = __shfl_sync(0xffffffffu, accS[j][0], srcB);
            float v11 = __shfl_sync(0xffffffffu, accS[j][1], srcB);
            float v12 = __shfl_sync(0xffffffffu, accS[j][2], srcB);
            float v13 = __shfl_sync(0xffffffffu, accS[j][3], srcB);
            uint32_t pa[4];
            pa[0] = f2tf(oddt ? v01 : v00);
            pa[1] = f2tf(oddt ? v03 : v02);
            pa[2] = f2tf(oddt ? v11 : v10);
            pa[3] = f2tf(oddt ? v13 : v12);
#pragma unroll
            for (int n2 = 0; n2 < 8; n2++) {
                const float* B = &smf[FOV + (j * 8 + t4) * FPW + n2 * 8 + g4];
                uint32_t b0 = *(const uint32_t*)&B[0];
                uint32_t b1 = *(const uint32_t*)&B[4 * FPW];
                MMATF(accO[n2], pa, b0, b1);
            }
        }
    }

    // ---- epilogue ----
    const float inv0 = 1.0f / l0;
    const float inv1 = 1.0f / l1;
    const int row = r0 + wid * 16 + g4;
    const size_t base0 = (brow + row) * (size_t)HEAD;
    const size_t base1 = (brow + row + 8) * (size_t)HEAD;
#pragma unroll
    for (int n = 0; n < 8; n++) {
        *(float2*)&out[base0 + n * 8 + qcol] =
            make_float2(accO[n][0] * inv0, accO[n][1] * inv0);
        *(float2*)&out[base1 + n * 8 + qcol] =
            make_float2(accO[n][2] * inv1, accO[n][3] * inv1);
    }
}

// ---------------------------------------------------------------------------
extern "C" void kernel_launch(void* const* d_in, const int* in_sizes, int n_in,
                              void* d_out, int out_size)
{
    const float* x  = (const float*)d_in[0];
    const float* Wq = (const float*)d_in[1];
    const float* Wk = (const float*)d_in[2];
    const float* Wv = (const float*)d_in[3];
    float* out = (float*)d_out;

    (void)in_sizes; (void)n_in; (void)out_size;

    cudaFuncSetAttribute(qkv_mma_kernel,
                         cudaFuncAttributeMaxDynamicSharedMemorySize,
                         QKV_SMEM_BYTES);
    cudaFuncSetAttribute(flash_kernel,
                         cudaFuncAttributeMaxDynamicSharedMemorySize,
                         FLASH_SMEM_BYTES);

    wprep_kernel<<<(NQKV * CEMB + 255) / 256, 256>>>(Wq, Wk, Wv);
    qkv_mma_kernel<<<MROWS / 64, 256, QKV_SMEM_BYTES>>>(x);
    flash_kernel<<<dim3(2, BATCH), 256, FLASH_SMEM_BYTES>>>(out);
}

// round 17
// speedup vs baseline: 8.0853x; 1.0264x over previous
#include <cuda_runtime.h>
#include <cuda_bf16.h>
#include <cstdint>

// Problem constants
#define BATCH 512
#define SEQ   256
#define CEMB  384
#define HEAD  64
#define MROWS (BATCH * SEQ)          // 131072
#define NQKV  (3 * HEAD)             // 192
#define SCALE 0.05103103630798288f   // 384^-0.5

// Scratch buffers (all values stored pre-rounded to tf32)
__device__ float g_WT[NQKV * CEMB];               // W^T [n][k]
__device__ float g_Q[(size_t)MROWS * HEAD];       // Q pre-scaled
__device__ float g_K[(size_t)MROWS * HEAD];
__device__ float g_V[(size_t)MROWS * HEAD];

// ---------------------------------------------------------------------------
// Helpers (baseline PTX, legal on .target sm_103)
// ---------------------------------------------------------------------------
__device__ __forceinline__ uint32_t smem_to_u32(const void* p) {
    uint32_t a;
    asm("{ .reg .u64 t; cvta.to.shared.u64 t, %1; cvt.u32.u64 %0, t; }"
        : "=r"(a) : "l"(p));
    return a;
}

__device__ __forceinline__ uint32_t f2tf(float f) {
    uint32_t u;
    asm("cvt.rna.tf32.f32 %0, %1;" : "=r"(u) : "f"(f));
    return u;
}

// D += A(m16k8, tf32) * B(k8n8, tf32)
#define MMATF(d, a, b0, b1) \
    asm volatile("mma.sync.aligned.m16n8k8.row.col.f32.tf32.tf32.f32 " \
        "{%0,%1,%2,%3}, {%4,%5,%6,%7}, {%8,%9}, {%0,%1,%2,%3};" \
        : "+f"((d)[0]), "+f"((d)[1]), "+f"((d)[2]), "+f"((d)[3]) \
        : "r"((a)[0]), "r"((a)[1]), "r"((a)[2]), "r"((a)[3]), \
          "r"(b0), "r"(b1))

#define CP_ASYNC16(dst_u32, src_ptr) \
    asm volatile("cp.async.cg.shared.global [%0], [%1], 16;" \
        :: "r"(dst_u32), "l"(src_ptr))
#define CP_COMMIT() asm volatile("cp.async.commit_group;")
#define CP_WAIT0()  asm volatile("cp.async.wait_group 0;" ::: "memory")

// ---------------------------------------------------------------------------
// Prep: W^T, rounded to tf32.  g_WT[n][k] = tf32(W[k][n]), n = mat*64 + h
// ---------------------------------------------------------------------------
__global__ void wprep_kernel(const float* __restrict__ Wq,
                             const float* __restrict__ Wk,
                             const float* __restrict__ Wv)
{
    int idx = blockIdx.x * 256 + threadIdx.x;
    if (idx >= NQKV * CEMB) return;
    int n = idx / CEMB, k = idx % CEMB;
    int mat = n >> 6, h = n & 63;
    const float* W = (mat == 0) ? Wq : (mat == 1) ? Wk : Wv;
    g_WT[idx] = __uint_as_float(f2tf(W[k * HEAD + h]));
}

// ---------------------------------------------------------------------------
// QKV projection, single-pass tf32 HMMA, double-buffered pipeline.
// BM=64, BN=192, BK=32; 256 threads; warps 2(M) x 4(N), warp tile 32x48.
// (unchanged from R15 — at the tensor-pipe issue floor)
// ---------------------------------------------------------------------------
#define QPW 36
#define A_F (64 * QPW)
#define B_F (192 * QPW)
#define STG (A_F + B_F)
#define OA(p) ((p) * STG)
#define OB(p) (OA(p) + A_F)
#define QKV_SMEM_BYTES (2 * STG * 4)  // 73728

__global__ __launch_bounds__(256, 2) void qkv_mma_kernel(const float* __restrict__ x)
{
    extern __shared__ float smq[];
    const uint32_t sbase = smem_to_u32(smq);
    const int tid   = threadIdx.x;
    const int lane  = tid & 31;
    const int wid   = tid >> 5;
    const int warpM = wid & 1;
    const int warpN = wid >> 1;
    const int row0  = blockIdx.x * 64;

    const int g4 = lane >> 2;
    const int t4 = lane & 3;
    const int ar = tid >> 2;
    const int ag = tid & 3;

    float acc[2][6][4];
#pragma unroll
    for (int mt = 0; mt < 2; mt++)
#pragma unroll
        for (int nt = 0; nt < 6; nt++)
#pragma unroll
            for (int e = 0; e < 4; e++) acc[mt][nt][e] = 0.0f;

    {
        const float4* s = (const float4*)&x[(size_t)(row0 + ar) * CEMB + ag * 8];
        float4 a0 = s[0], a1 = s[1];
        uint4 w0 = make_uint4(f2tf(a0.x), f2tf(a0.y), f2tf(a0.z), f2tf(a0.w));
        uint4 w1 = make_uint4(f2tf(a1.x), f2tf(a1.y), f2tf(a1.z), f2tf(a1.w));
        *(uint4*)&smq[OA(0) + ar * QPW + ag * 8]     = w0;
        *(uint4*)&smq[OA(0) + ar * QPW + ag * 8 + 4] = w1;
#pragma unroll
        for (int i = 0; i < 6; i++) {
            int li = tid + i * 256;
            int r = li >> 3, g = li & 7;
            CP_ASYNC16(sbase + (OB(0) + r * QPW + g * 4) * 4,
                       (const void*)&g_WT[(size_t)r * CEMB + g * 4]);
        }
        CP_COMMIT();
        CP_WAIT0();
        __syncthreads();
    }

    for (int c = 0; c < 12; c++) {
        const int p = c & 1;
        const bool pre = (c < 11);
        float4 pa0, pa1;
        if (pre) {
            const int k1 = (c + 1) * 32;
            const float4* s = (const float4*)&x[(size_t)(row0 + ar) * CEMB + k1 + ag * 8];
            pa0 = s[0]; pa1 = s[1];
#pragma unroll
            for (int i = 0; i < 6; i++) {
                int li = tid + i * 256;
                int r = li >> 3, g = li & 7;
                CP_ASYNC16(sbase + (OB(p ^ 1) + r * QPW + g * 4) * 4,
                           (const void*)&g_WT[(size_t)r * CEMB + k1 + g * 4]);
            }
            CP_COMMIT();
        }

#pragma unroll
        for (int ks = 0; ks < 4; ks++) {
            const int kk = ks * 8;
            uint32_t af[2][4];
#pragma unroll
            for (int mt = 0; mt < 2; mt++) {
                const int m = warpM * 32 + mt * 16;
                const float* A = &smq[OA(p) + kk + t4];
                af[mt][0] = *(const uint32_t*)&A[(m + g4) * QPW];
                af[mt][1] = *(const uint32_t*)&A[(m + g4 + 8) * QPW];
                af[mt][2] = *(const uint32_t*)&A[(m + g4) * QPW + 4];
                af[mt][3] = *(const uint32_t*)&A[(m + g4 + 8) * QPW + 4];
            }
            uint32_t bf[6][2];
#pragma unroll
            for (int j = 0; j < 6; j++) {
                const int n = warpN * 48 + j * 8;
                const float* B = &smq[OB(p) + (n + g4) * QPW + kk + t4];
                bf[j][0] = *(const uint32_t*)&B[0];
                bf[j][1] = *(const uint32_t*)&B[4];
            }
#pragma unroll
            for (int mt = 0; mt < 2; mt++)
#pragma unroll
                for (int j = 0; j < 6; j++)
                    MMATF(acc[mt][j], af[mt], bf[j][0], bf[j][1]);
        }

        if (pre) {
            uint4 w0 = make_uint4(f2tf(pa0.x), f2tf(pa0.y), f2tf(pa0.z), f2tf(pa0.w));
            uint4 w1 = make_uint4(f2tf(pa1.x), f2tf(pa1.y), f2tf(pa1.z), f2tf(pa1.w));
            *(uint4*)&smq[OA(p ^ 1) + ar * QPW + ag * 8]     = w0;
            *(uint4*)&smq[OA(p ^ 1) + ar * QPW + ag * 8 + 4] = w1;
            CP_WAIT0();
        }
        __syncthreads();
    }

#pragma unroll
    for (int mt = 0; mt < 2; mt++) {
#pragma unroll
        for (int h = 0; h < 2; h++) {
            int row = row0 + warpM * 32 + mt * 16 + g4 + 8 * h;
#pragma unroll
            for (int j = 0; j < 6; j++) {
                int n = warpN * 48 + j * 8 + t4 * 2;
                int mat = n >> 6;
                int cc  = n & 63;
                float v0 = acc[mt][j][2 * h];
                float v1 = acc[mt][j][2 * h + 1];
                if (mat == 0) { v0 *= SCALE; v1 *= SCALE; }
                float* dst = (mat == 0) ? g_Q : (mat == 1) ? g_K : g_V;
                *(float2*)&dst[(size_t)row * HEAD + cc] =
                    make_float2(__uint_as_float(f2tf(v0)), __uint_as_float(f2tf(v1)));
            }
        }
    }
}

// ---------------------------------------------------------------------------
// Flash-attention-2, single-pass tf32, K/V double-buffered via cp.async.
// Block = (128-row tile, batch). 8 warps x 16 rows. Online softmax.
// One syncthreads per chunk; gmem latency hidden behind compute.
// ---------------------------------------------------------------------------
#define FPW 68
#define QBUF (128 * FPW)              // 8704 floats
#define KBUF (64 * FPW)               // 4352 floats
#define FOQ 0
#define FOK(p) (QBUF + (p) * 2 * KBUF)
#define FOV(p) (FOK(p) + KBUF)
#define FLASH_SMEM_BYTES ((QBUF + 4 * KBUF) * 4)   // 104448

__global__ __launch_bounds__(256, 2) void flash_kernel(float* __restrict__ out)
{
    extern __shared__ float smf[];
    const uint32_t sb = smem_to_u32(smf);
    const int tid = threadIdx.x, lane = tid & 31, wid = tid >> 5;
    const int rt = blockIdx.x, batch = blockIdx.y;
    const int r0 = rt * 128;
    const size_t brow = (size_t)batch * SEQ;
    const int g4 = lane >> 2;
    const int t4 = lane & 3;
    const int qcol = t4 * 2;

    // Prologue: Q tile + K/V chunk 0, all via cp.async, one group.
#pragma unroll
    for (int i = 0; i < 8; i++) {
        int li = tid + i * 256;
        int r = li >> 4, g = li & 15;
        CP_ASYNC16(sb + (FOQ + r * FPW + g * 4) * 4,
                   (const void*)&g_Q[(brow + r0 + r) * HEAD + g * 4]);
    }
#pragma unroll
    for (int i = 0; i < 4; i++) {
        int li = tid + i * 256;
        int r = li >> 4, g = li & 15;
        size_t src = (brow + r) * HEAD + g * 4;
        CP_ASYNC16(sb + (FOK(0) + r * FPW + g * 4) * 4, (const void*)&g_K[src]);
        CP_ASYNC16(sb + (FOV(0) + r * FPW + g * 4) * 4, (const void*)&g_V[src]);
    }
    CP_COMMIT();

    float accO[8][4];
#pragma unroll
    for (int n = 0; n < 8; n++)
#pragma unroll
        for (int e = 0; e < 4; e++) accO[n][e] = 0.0f;
    float m0 = -1e30f, m1 = -1e30f, l0 = 0.0f, l1 = 0.0f;

    const int nch = 2 * (rt + 1);
    for (int kc = 0; kc < nch; kc++) {
        const int p = kc & 1;
        // buffer p's data has arrived; barrier also guarantees everyone is
        // done computing from buffer p^1 before we overwrite it below.
        CP_WAIT0();
        __syncthreads();
        if (kc + 1 < nch) {
#pragma unroll
            for (int i = 0; i < 4; i++) {
                int li = tid + i * 256;
                int r = li >> 4, g = li & 15;
                size_t src = (brow + (kc + 1) * 64 + r) * HEAD + g * 4;
                CP_ASYNC16(sb + (FOK(p ^ 1) + r * FPW + g * 4) * 4,
                           (const void*)&g_K[src]);
                CP_ASYNC16(sb + (FOV(p ^ 1) + r * FPW + g * 4) * 4,
                           (const void*)&g_V[src]);
            }
            CP_COMMIT();
        }

        // ---- S = Q K^T ----
        float accS[8][4];
#pragma unroll
        for (int n = 0; n < 8; n++)
#pragma unroll
            for (int e = 0; e < 4; e++) accS[n][e] = 0.0f;

        const int mrow = wid * 16;
#pragma unroll
        for (int ks = 0; ks < 8; ks++) {
            const int kk = ks * 8;
            uint32_t af[4];
            {
                const float* A = &smf[FOQ + kk + t4];
                af[0] = *(const uint32_t*)&A[(mrow + g4) * FPW];
                af[1] = *(const uint32_t*)&A[(mrow + g4 + 8) * FPW];
                af[2] = *(const uint32_t*)&A[(mrow + g4) * FPW + 4];
                af[3] = *(const uint32_t*)&A[(mrow + g4 + 8) * FPW + 4];
            }
#pragma unroll
            for (int n2 = 0; n2 < 8; n2++) {
                const float* B = &smf[FOK(p) + (n2 * 8 + g4) * FPW + kk + t4];
                uint32_t b0 = *(const uint32_t*)&B[0];
                uint32_t b1 = *(const uint32_t*)&B[4];
                MMATF(accS[n2], af, b0, b1);
            }
        }

        // ---- mask + online softmax update ----
        const int c0 = kc * 64;
#pragma unroll
        for (int h = 0; h < 2; h++) {
            const int gi = r0 + wid * 16 + g4 + 8 * h;
            float& m = (h == 0) ? m0 : m1;
            float& l = (h == 0) ? l0 : l1;
            float mx = -1e30f;
#pragma unroll
            for (int n = 0; n < 8; n++) {
                int col = c0 + n * 8 + qcol;
                if (col > gi)     accS[n][2 * h]     = -1e30f;
                if (col + 1 > gi) accS[n][2 * h + 1] = -1e30f;
                mx = fmaxf(mx, fmaxf(accS[n][2 * h], accS[n][2 * h + 1]));
            }
            mx = fmaxf(mx, __shfl_xor_sync(0xffffffffu, mx, 1));
            mx = fmaxf(mx, __shfl_xor_sync(0xffffffffu, mx, 2));
            float mn = fmaxf(m, mx);
            float sc = __expf(m - mn);
            float sum = 0.0f;
#pragma unroll
            for (int n = 0; n < 8; n++) {
                float p0 = __expf(accS[n][2 * h]     - mn);
                float p1 = __expf(accS[n][2 * h + 1] - mn);
                accS[n][2 * h] = p0;
                accS[n][2 * h + 1] = p1;
                sum += p0 + p1;
            }
            sum += __shfl_xor_sync(0xffffffffu, sum, 1);
            sum += __shfl_xor_sync(0xffffffffu, sum, 2);
            l = l * sc + sum;
            m = mn;
#pragma unroll
            for (int n = 0; n < 8; n++) {
                accO[n][2 * h]     *= sc;
                accO[n][2 * h + 1] *= sc;
            }
        }

        // ---- O += P V : C-frag -> A-frag quad shuffle, then MMA ----
        const int srcA = (lane & ~3) | (t4 >> 1);
        const int srcB = srcA + 2;
        const bool oddt = (t4 & 1);
#pragma unroll
        for (int j = 0; j < 8; j++) {
            float v00 = __shfl_sync(0xffffffffu, accS[j][0], srcA);
            float v01 = __shfl_sync(0xffffffffu, accS[j][1], srcA);
            float v02 = __shfl_sync(0xffffffffu, accS[j][2], srcA);
            float v03 = __shfl_sync(0xffffffffu, accS[j][3], srcA);
            float v10 = __shfl_sync(0xffffffffu, accS[j][0], srcB);
            float v11 = __shfl_sync(0xffffffffu, accS[j][1], srcB);
            float v12 = __shfl_sync(0xffffffffu, accS[j][2], srcB);
            float v13 = __shfl_sync(0xffffffffu, accS[j][3], srcB);
            uint32_t pa[4];
            pa[0] = f2tf(oddt ? v01 : v00);
            pa[1] = f2tf(oddt ? v03 : v02);
            pa[2] = f2tf(oddt ? v11 : v10);
            pa[3] = f2tf(oddt ? v13 : v12);
#pragma unroll
            for (int n2 = 0; n2 < 8; n2++) {
                const float* B = &smf[FOV(p) + (j * 8 + t4) * FPW + n2 * 8 + g4];
                uint32_t b0 = *(const uint32_t*)&B[0];
                uint32_t b1 = *(const uint32_t*)&B[4 * FPW];
                MMATF(accO[n2], pa, b0, b1);
            }
        }
    }

    // ---- epilogue ----
    const float inv0 = 1.0f / l0;
    const float inv1 = 1.0f / l1;
    const int row = r0 + wid * 16 + g4;
    const size_t base0 = (brow + row) * (size_t)HEAD;
    const size_t base1 = (brow + row + 8) * (size_t)HEAD;
#pragma unroll
    for (int n = 0; n < 8; n++) {
        *(float2*)&out[base0 + n * 8 + qcol] =
            make_float2(accO[n][0] * inv0, accO[n][1] * inv0);
        *(float2*)&out[base1 + n * 8 + qcol] =
            make_float2(accO[n][2] * inv1, accO[n][3] * inv1);
    }
}

// ---------------------------------------------------------------------------
extern "C" void kernel_launch(void* const* d_in, const int* in_sizes, int n_in,
                              void* d_out, int out_size)
{
    const float* x  = (const float*)d_in[0];
    const float* Wq = (const float*)d_in[1];
    const float* Wk = (const float*)d_in[2];
    const float* Wv = (const float*)d_in[3];
    float* out = (float*)d_out;

    (void)in_sizes; (void)n_in; (void)out_size;

    cudaFuncSetAttribute(qkv_mma_kernel,
                         cudaFuncAttributeMaxDynamicSharedMemorySize,
                         QKV_SMEM_BYTES);
    cudaFuncSetAttribute(flash_kernel,
                         cudaFuncAttributeMaxDynamicSharedMemorySize,
                         FLASH_SMEM_BYTES);

    wprep_kernel<<<(NQKV * CEMB + 255) / 256, 256>>>(Wq, Wk, Wv);
    qkv_mma_kernel<<<MROWS / 64, 256, QKV_SMEM_BYTES>>>(x);
    flash_kernel<<<dim3(2, BATCH), 256, FLASH_SMEM_BYTES>>>(out);
}